// round 10
// baseline (speedup 1.0000x reference)
#include <cuda_runtime.h>
#include <cuda_fp16.h>
#include <cstdint>
#include <cstddef>

// ============================ problem constants ============================
#define D_IN   1024
#define NH1    4096
#define NH2    512
#define D_OUT  256
#define NROWS  16384

// ============================ tiling =======================================
#define BM 128
#define BN 128
#define BK 64                        // fp16: row = 128B
#define NSTG 3
#define STAGE_B 32768                // (BM+BN)*BK*2 bytes
#define B_OFF   16384                // B tile offset within a stage
#define NTHR 128                     // 4 warps, warp tile 64x64
#define NC1  (D_IN / BK)             // 16 k-chunks (fc1)
#define NC3  (NH2 / BK)              // 8 k-chunks (fc3)
#define ES_OFF 98304                 // epilogue buffer (3 stages end)
#define MB_OFF 108544                // fc1 mbarriers: full[3] then empty[3]
#define MB3_OFF 98304                // fc3 mbarriers

// ============================ scratch ======================================
__device__ __align__(1024) __half g_Xh [NROWS * D_IN];
__device__ __align__(1024) __half g_W1h[NH1 * D_IN];
__device__ __align__(1024) __half g_W3h[D_OUT * NH2];
__device__ __align__(1024) __half g_x2h[NROWS * NH2];

// ============================ device helpers ===============================
__device__ __forceinline__ uint32_t sm32(const void* p) {
    uint32_t a;
    asm("{ .reg .u64 t; cvta.to.shared.u64 t, %1; cvt.u32.u64 %0, t; }"
        : "=r"(a) : "l"(p));
    return a;
}
__device__ __forceinline__ void cpa16(uint32_t d, const void* s) {
    asm volatile("cp.async.cg.shared.global [%0], [%1], 16;" :: "r"(d), "l"(s));
}

#define MBAR_INIT(addr, cnt) \
    asm volatile("mbarrier.init.shared.b64 [%0], %1;" :: "r"(addr), "r"(cnt) : "memory")
#define MBAR_ARRIVE(addr) \
    asm volatile("mbarrier.arrive.shared.b64 _, [%0];" :: "r"(addr) : "memory")
// .noinc is REQUIRED: the default form is self-balancing and never completes.
#define CP_MBAR_ARRIVE(addr) \
    asm volatile("cp.async.mbarrier.arrive.noinc.shared.b64 [%0];" :: "r"(addr) : "memory")

__device__ __forceinline__ void mbar_wait(uint32_t mbar, uint32_t parity) {
    asm volatile(
        "{\n\t.reg .pred P;\n\t"
        "LW_%=:\n\t"
        "mbarrier.try_wait.parity.acquire.cta.shared::cta.b64 P, [%0], %1, 0x989680;\n\t"
        "@P bra.uni LD_%=;\n\t"
        "bra.uni LW_%=;\n\t"
        "LD_%=:\n\t}"
        :: "r"(mbar), "r"(parity) : "memory");
}
// producer-side wait: post-wait writes are async-proxy (cp.async) only
__device__ __forceinline__ void mbar_wait_relaxed(uint32_t mbar, uint32_t parity) {
    asm volatile(
        "{\n\t.reg .pred P;\n\t"
        "LW_%=:\n\t"
        "mbarrier.try_wait.parity.relaxed.cta.shared::cta.b64 P, [%0], %1, 0x989680;\n\t"
        "@P bra.uni LD_%=;\n\t"
        "bra.uni LW_%=;\n\t"
        "LD_%=:\n\t}"
        :: "r"(mbar), "r"(parity) : "memory");
}

__device__ __forceinline__ void ldsm4(uint32_t* d, uint32_t a) {
    asm volatile("ldmatrix.sync.aligned.m8n8.x4.shared.b16 {%0,%1,%2,%3}, [%4];"
        : "=r"(d[0]), "=r"(d[1]), "=r"(d[2]), "=r"(d[3]) : "r"(a));
}
__device__ __forceinline__ void mma16(float* c, const uint32_t* a, const uint32_t* b) {
    asm volatile("mma.sync.aligned.m16n8k16.row.col.f32.f16.f16.f32 "
        "{%0,%1,%2,%3}, {%4,%5,%6,%7}, {%8,%9}, {%0,%1,%2,%3};"
        : "+f"(c[0]), "+f"(c[1]), "+f"(c[2]), "+f"(c[3])
        : "r"(a[0]), "r"(a[1]), "r"(a[2]), "r"(a[3]), "r"(b[0]), "r"(b[1]));
}
__device__ __forceinline__ float sigm(float x) {
    return __fdividef(1.f, 1.f + __expf(-x));
}

// ============================ fp32 -> fp16 convert =========================
__global__ void cvt_kernel(const float4* __restrict__ s, uint2* __restrict__ d, int n4) {
    int i = blockIdx.x * blockDim.x + threadIdx.x;
    if (i < n4) {
        float4 v = s[i];
        __half2 h0 = __floats2half2_rn(v.x, v.y);
        __half2 h1 = __floats2half2_rn(v.z, v.w);
        uint2 o;
        o.x = *(uint32_t*)&h0;
        o.y = *(uint32_t*)&h1;
        d[i] = o;
    }
}

// ============================ stage load ===================================
// smem element (row r, k): byte = r*128 + (((k>>3) ^ (r&7))<<4) + (k&7)*2
template<int KDIM>
__device__ __forceinline__ void stage_load(
    const __half* __restrict__ A, const __half* __restrict__ B,
    int m0, int n0, int kc, int s, uint32_t sb, int tid)
{
    const uint32_t so = sb + (uint32_t)(s * STAGE_B);
    #pragma unroll
    for (int i = 0; i < 8; ++i) {                 // A: 128 rows x 8 x 16B
        int id = tid + i * NTHR;
        int r = id >> 3, u = id & 7;
        cpa16(so + r * 128 + ((u ^ (r & 7)) << 4),
              A + (size_t)(m0 + r) * KDIM + kc * BK + u * 8);
    }
    #pragma unroll
    for (int i = 0; i < 8; ++i) {                 // B: 128 rows x 8 x 16B
        int id = tid + i * NTHR;
        int r = id >> 3, u = id & 7;
        cpa16(so + B_OFF + r * 128 + ((u ^ (r & 7)) << 4),
              B + (size_t)(n0 + r) * KDIM + kc * BK + u * 8);
    }
}

// ============================ fc1: mbarrier pipeline, de-correlated heads ==
// Chunk body: full-wait -> ks0 -> (producer: empty-wait+load+arrive) -> ks1-3.
// Per-warp ks rotation spreads the post-flip ldsm bursts and HMMA heads.
__global__ void __launch_bounds__(NTHR, 2) fc1_kernel(
    const __half* __restrict__ X,  const __half* __restrict__ W1,
    const float* __restrict__ b1,  const float* __restrict__ W2,
    const float* __restrict__ b2,  __half* __restrict__ x2)
{
    extern __shared__ float sm[];
    const uint32_t sb = sm32(sm);
    const int tid = threadIdx.x, lane = tid & 31, wid = tid >> 5;
    const int wm = wid >> 1, wn = wid & 1;
    const int m0 = blockIdx.y * BM, n0 = blockIdx.x * BN;
    const uint32_t mbf = sb + MB_OFF;              // full[3]
    const uint32_t mbe = sb + MB_OFF + 24;         // empty[3]

    if (tid == 0) {
        #pragma unroll
        for (int s = 0; s < NSTG; ++s) {
            MBAR_INIT(mbf + 8 * s, NTHR);          // 128 .noinc cp-arrives
            MBAR_INIT(mbe + 8 * s, 4);             // one arrive per warp
        }
    }
    __syncthreads();

    const int lr = lane & 7, j = lane >> 3;
    const int jlow = j & 1, jhi = j >> 1;
    uint32_t baseA[4], baseB[4];
    #pragma unroll
    for (int mt = 0; mt < 4; ++mt)
        baseA[mt] = (uint32_t)((wm * 64 + mt * 16 + (jlow << 3) + lr) * 128);
    #pragma unroll
    for (int p = 0; p < 4; ++p)
        baseB[p] = (uint32_t)(B_OFF + (wn * 64 + (2 * p + jhi) * 8 + lr) * 128);

    float acc[4][8][4];
    #pragma unroll
    for (int i = 0; i < 4; ++i)
        #pragma unroll
        for (int j2 = 0; j2 < 8; ++j2)
            #pragma unroll
            for (int k = 0; k < 4; ++k) acc[i][j2][k] = 0.f;

    // one ks step of the 64x64 warp tile on stage 'stg'
    auto do_ks = [&](uint32_t stg, int kse) {
        const uint32_t swzA = (uint32_t)(((2 * kse + jhi) ^ lr) << 4);
        const uint32_t swzB = (uint32_t)(((2 * kse + jlow) ^ lr) << 4);
        uint32_t a[4][4], b[4][4];
        #pragma unroll
        for (int mt = 0; mt < 4; ++mt) ldsm4(a[mt], stg + baseA[mt] + swzA);
        #pragma unroll
        for (int p = 0; p < 4; ++p)    ldsm4(b[p],  stg + baseB[p] + swzB);
        #pragma unroll
        for (int mt = 0; mt < 4; ++mt) {
            #pragma unroll
            for (int p = 0; p < 4; ++p) {
                mma16(acc[mt][2 * p],     a[mt], &b[p][0]);
                mma16(acc[mt][2 * p + 1], a[mt], &b[p][2]);
            }
        }
    };

    // ---- prologue: fill stages 0,1 ----
    stage_load<D_IN>(X, W1, m0, n0, 0, 0, sb, tid);
    CP_MBAR_ARRIVE(mbf + 0);
    stage_load<D_IN>(X, W1, m0, n0, 1, 1, sb, tid);
    CP_MBAR_ARRIVE(mbf + 8);

    int lc = 2;                                    // next chunk to load
    #pragma unroll 1
    for (int c = 0; c < NC1; ++c) {
        const int cf = c / NSTG;
        const int cs = c - cf * NSTG;
        mbar_wait(mbf + 8 * cs, (uint32_t)(cf & 1));
        const uint32_t stg = sb + (uint32_t)cs * STAGE_B;

        do_ks(stg, wid & 3);                       // ks0 (rotated per warp)

        // producer block issues under tensor work
        if (lc < NC1) {
            const int lf = lc / NSTG;
            const int lss = lc - lf * NSTG;
            if (lc >= NSTG) mbar_wait_relaxed(mbe + 8 * lss, (uint32_t)((lf - 1) & 1));
            stage_load<D_IN>(X, W1, m0, n0, lc, lss, sb, tid);
            CP_MBAR_ARRIVE(mbf + 8 * lss);
            ++lc;
        }

        do_ks(stg, (wid + 1) & 3);
        do_ks(stg, (wid + 2) & 3);
        do_ks(stg, (wid + 3) & 3);

        __syncwarp();
        if (lane == 0) MBAR_ARRIVE(mbe + 8 * cs);  // warp done with stage cs
    }

    // -------- fused epilogue: bias+sigmoid -> grouped dot (quad shfl) ------
    const int q = lane & 3, g2 = lane >> 2;
    const int ntile = blockIdx.x;
    float* es = sm + ES_OFF / 4;                   // dedicated buffer

    float b1v[16], w2v[16];
    #pragma unroll
    for (int nt = 0; nt < 8; ++nt) {
        int cidx = n0 + wn * 64 + nt * 8 + 2 * q;
        b1v[2 * nt]     = __ldg(b1 + cidx);
        b1v[2 * nt + 1] = __ldg(b1 + cidx + 1);
        w2v[2 * nt]     = __ldg(W2 + cidx);
        w2v[2 * nt + 1] = __ldg(W2 + cidx + 1);
    }
    const float b2v0 = __ldg(b2 + ntile * 16 + wn * 8 + q);
    const float b2v1 = __ldg(b2 + ntile * 16 + wn * 8 + q + 4);

    #pragma unroll
    for (int mt = 0; mt < 4; ++mt) {
        #pragma unroll
        for (int nt = 0; nt < 8; ++nt) {
            float h00 = sigm(acc[mt][nt][0] + b1v[2 * nt]);
            float h01 = sigm(acc[mt][nt][1] + b1v[2 * nt + 1]);
            float h10 = sigm(acc[mt][nt][2] + b1v[2 * nt]);
            float h11 = sigm(acc[mt][nt][3] + b1v[2 * nt + 1]);
            float p0 = h00 * w2v[2 * nt] + h01 * w2v[2 * nt + 1];
            float p1 = h10 * w2v[2 * nt] + h11 * w2v[2 * nt + 1];
            p0 += __shfl_xor_sync(0xffffffffu, p0, 1);
            p0 += __shfl_xor_sync(0xffffffffu, p0, 2);
            p1 += __shfl_xor_sync(0xffffffffu, p1, 1);
            p1 += __shfl_xor_sync(0xffffffffu, p1, 2);
            if (q == (nt & 3)) {
                int g  = wn * 8 + nt;              // 16 groups per CTA
                int r0 = wm * 64 + mt * 16 + g2;
                float bv = (nt < 4) ? b2v0 : b2v1;
                es[r0 * 20 + g]       = sigm(p0 + bv);
                es[(r0 + 8) * 20 + g] = sigm(p1 + bv);
            }
        }
    }
    __syncthreads();

    // coalesced fp16 store: 128 rows x 16 groups; 1 thread per row
    {
        const float* e = es + tid * 20;
        __half2 h0 = __floats2half2_rn(e[0],  e[1]);
        __half2 h1 = __floats2half2_rn(e[2],  e[3]);
        __half2 h2 = __floats2half2_rn(e[4],  e[5]);
        __half2 h3 = __floats2half2_rn(e[6],  e[7]);
        __half2 h4 = __floats2half2_rn(e[8],  e[9]);
        __half2 h5 = __floats2half2_rn(e[10], e[11]);
        __half2 h6 = __floats2half2_rn(e[12], e[13]);
        __half2 h7 = __floats2half2_rn(e[14], e[15]);
        uint4 o0, o1;
        o0.x = *(uint32_t*)&h0; o0.y = *(uint32_t*)&h1;
        o0.z = *(uint32_t*)&h2; o0.w = *(uint32_t*)&h3;
        o1.x = *(uint32_t*)&h4; o1.y = *(uint32_t*)&h5;
        o1.z = *(uint32_t*)&h6; o1.w = *(uint32_t*)&h7;
        __half* dst = x2 + (size_t)(m0 + tid) * NH2 + ntile * 16;
        *(uint4*)dst       = o0;
        *(uint4*)(dst + 8) = o1;
    }
}

// ============================ fc3: same mbar pipeline ======================
__global__ void __launch_bounds__(NTHR, 2) fc3_kernel(
    const __half* __restrict__ A,  const __half* __restrict__ W3,
    const float* __restrict__ b3,  float* __restrict__ out)
{
    extern __shared__ float sm[];
    const uint32_t sb = sm32(sm);
    const int tid = threadIdx.x, lane = tid & 31, wid = tid >> 5;
    const int wm = wid >> 1, wn = wid & 1;
    const int m0 = blockIdx.y * BM, n0 = blockIdx.x * BN;
    const uint32_t mbf = sb + MB3_OFF;
    const uint32_t mbe = sb + MB3_OFF + 24;

    if (tid == 0) {
        #pragma unroll
        for (int s = 0; s < NSTG; ++s) {
            MBAR_INIT(mbf + 8 * s, NTHR);
            MBAR_INIT(mbe + 8 * s, 4);
        }
    }
    __syncthreads();

    const int lr = lane & 7, j = lane >> 3;
    const int jlow = j & 1, jhi = j >> 1;
    uint32_t baseA[4], baseB[4];
    #pragma unroll
    for (int mt = 0; mt < 4; ++mt)
        baseA[mt] = (uint32_t)((wm * 64 + mt * 16 + (jlow << 3) + lr) * 128);
    #pragma unroll
    for (int p = 0; p < 4; ++p)
        baseB[p] = (uint32_t)(B_OFF + (wn * 64 + (2 * p + jhi) * 8 + lr) * 128);

    float acc[4][8][4];
    #pragma unroll
    for (int i = 0; i < 4; ++i)
        #pragma unroll
        for (int j2 = 0; j2 < 8; ++j2)
            #pragma unroll
            for (int k = 0; k < 4; ++k) acc[i][j2][k] = 0.f;

    auto do_ks = [&](uint32_t stg, int kse) {
        const uint32_t swzA = (uint32_t)(((2 * kse + jhi) ^ lr) << 4);
        const uint32_t swzB = (uint32_t)(((2 * kse + jlow) ^ lr) << 4);
        uint32_t a[4][4], b[4][4];
        #pragma unroll
        for (int mt = 0; mt < 4; ++mt) ldsm4(a[mt], stg + baseA[mt] + swzA);
        #pragma unroll
        for (int p = 0; p < 4; ++p)    ldsm4(b[p],  stg + baseB[p] + swzB);
        #pragma unroll
        for (int mt = 0; mt < 4; ++mt) {
            #pragma unroll
            for (int p = 0; p < 4; ++p) {
                mma16(acc[mt][2 * p],     a[mt], &b[p][0]);
                mma16(acc[mt][2 * p + 1], a[mt], &b[p][2]);
            }
        }
    };

    stage_load<NH2>(A, W3, m0, n0, 0, 0, sb, tid);
    CP_MBAR_ARRIVE(mbf + 0);
    stage_load<NH2>(A, W3, m0, n0, 1, 1, sb, tid);
    CP_MBAR_ARRIVE(mbf + 8);

    int lc = 2;
    #pragma unroll 1
    for (int c = 0; c < NC3; ++c) {
        const int cf = c / NSTG;
        const int cs = c - cf * NSTG;
        mbar_wait(mbf + 8 * cs, (uint32_t)(cf & 1));
        const uint32_t stg = sb + (uint32_t)cs * STAGE_B;

        do_ks(stg, wid & 3);
        if (lc < NC3) {
            const int lf = lc / NSTG;
            const int lss = lc - lf * NSTG;
            if (lc >= NSTG) mbar_wait_relaxed(mbe + 8 * lss, (uint32_t)((lf - 1) & 1));
            stage_load<NH2>(A, W3, m0, n0, lc, lss, sb, tid);
            CP_MBAR_ARRIVE(mbf + 8 * lss);
            ++lc;
        }
        do_ks(stg, (wid + 1) & 3);
        do_ks(stg, (wid + 2) & 3);
        do_ks(stg, (wid + 3) & 3);

        __syncwarp();
        if (lane == 0) MBAR_ARRIVE(mbe + 8 * cs);
    }

    const int q = lane & 3, g2 = lane >> 2;
    #pragma unroll
    for (int mt = 0; mt < 4; ++mt) {
        #pragma unroll
        for (int nt = 0; nt < 8; ++nt) {
            int cl = wn * 64 + nt * 8 + 2 * q;
            int r0 = m0 + wm * 64 + mt * 16 + g2;
            float bb0 = __ldg(b3 + n0 + cl);
            float bb1 = __ldg(b3 + n0 + cl + 1);
            float2 v0 = make_float2(acc[mt][nt][0] + bb0, acc[mt][nt][1] + bb1);
            float2 v1 = make_float2(acc[mt][nt][2] + bb0, acc[mt][nt][3] + bb1);
            *(float2*)(out + (size_t)r0 * D_OUT + n0 + cl)       = v0;
            *(float2*)(out + (size_t)(r0 + 8) * D_OUT + n0 + cl) = v1;
        }
    }
}

// ============================ host =========================================
extern "C" void kernel_launch(void* const* d_in, const int* in_sizes, int n_in,
                              void* d_out, int out_size) {
    (void)in_sizes; (void)n_in; (void)out_size;
    const float* x  = (const float*)d_in[0];
    const float* W1 = (const float*)d_in[1];
    const float* b1 = (const float*)d_in[2];
    const float* W2 = (const float*)d_in[3];
    const float* b2 = (const float*)d_in[4];
    const float* W3 = (const float*)d_in[5];
    const float* b3 = (const float*)d_in[6];
    float* out = (float*)d_out;

    void *pXh = nullptr, *pW1h = nullptr, *pW3h = nullptr, *px2h = nullptr;
    cudaGetSymbolAddress(&pXh,  g_Xh);
    cudaGetSymbolAddress(&pW1h, g_W1h);
    cudaGetSymbolAddress(&pW3h, g_W3h);
    cudaGetSymbolAddress(&px2h, g_x2h);

    const int smem1 = MB_OFF + 64;                    // 108608 B
    const int smem3 = MB3_OFF + 64;                   //  98368 B
    cudaFuncSetAttribute(fc1_kernel, cudaFuncAttributeMaxDynamicSharedMemorySize, smem1);
    cudaFuncSetAttribute(fc3_kernel, cudaFuncAttributeMaxDynamicSharedMemorySize, smem3);

    {
        int n4 = NROWS * D_IN / 4;
        cvt_kernel<<<(n4 + 255) / 256, 256>>>((const float4*)x, (uint2*)pXh, n4);
        n4 = NH1 * D_IN / 4;
        cvt_kernel<<<(n4 + 255) / 256, 256>>>((const float4*)W1, (uint2*)pW1h, n4);
        n4 = D_OUT * NH2 / 4;
        cvt_kernel<<<(n4 + 255) / 256, 256>>>((const float4*)W3, (uint2*)pW3h, n4);
    }

    fc1_kernel<<<dim3(NH1 / BN, NROWS / BM), NTHR, smem1>>>(
        (const __half*)pXh, (const __half*)pW1h, b1, W2, b2, (__half*)px2h);
    fc3_kernel<<<dim3(D_OUT / BN, NROWS / BM), NTHR, smem3>>>(
        (const __half*)px2h, (const __half*)pW3h, b3, out);
}

// round 11
// speedup vs baseline: 1.0287x; 1.0287x over previous
#include <cuda_runtime.h>
#include <cuda_fp16.h>
#include <cstdint>
#include <cstddef>

// ============================ problem constants ============================
#define D_IN   1024
#define NH1    4096
#define NH2    512
#define D_OUT  256
#define NROWS  16384

// ============================ tiling =======================================
#define BM 128
#define BN 128
#define BK 64                        // fp16: row = 128B
#define NSTG 3
#define STAGE_B 32768                // (BM+BN)*BK*2 bytes
#define B_OFF   16384                // B tile offset within a stage
#define NTHR 128                     // 4 warps, warp tile 64x64
#define NC1  (D_IN / BK)             // 16 k-chunks (fc1)
#define NC3  (NH2 / BK)              // 8 k-chunks (fc3)
#define ES_OFF 98304                 // epilogue buffer (3 stages end)
#define MB_OFF 108544                // fc1 mbarriers: full[3] then empty[3]
#define MB3_OFF 98304                // fc3 mbarriers

// cvt segment sizes (in float4 units)
#define N4_X  (NROWS * D_IN / 4)     // 4194304
#define N4_W1 (NH1 * D_IN / 4)       // 1048576
#define N4_W3 (D_OUT * NH2 / 4)      // 32768
#define N4_ALL (N4_X + N4_W1 + N4_W3)

// ============================ scratch ======================================
__device__ __align__(1024) __half g_Xh [NROWS * D_IN];
__device__ __align__(1024) __half g_W1h[NH1 * D_IN];
__device__ __align__(1024) __half g_W3h[D_OUT * NH2];
__device__ __align__(1024) __half g_x2h[NROWS * NH2];

// ============================ device helpers ===============================
__device__ __forceinline__ uint32_t sm32(const void* p) {
    uint32_t a;
    asm("{ .reg .u64 t; cvta.to.shared.u64 t, %1; cvt.u32.u64 %0, t; }"
        : "=r"(a) : "l"(p));
    return a;
}
__device__ __forceinline__ void cpa16(uint32_t d, const void* s) {
    asm volatile("cp.async.cg.shared.global [%0], [%1], 16;" :: "r"(d), "l"(s));
}

#define MBAR_INIT(addr, cnt) \
    asm volatile("mbarrier.init.shared.b64 [%0], %1;" :: "r"(addr), "r"(cnt) : "memory")
#define MBAR_ARRIVE(addr) \
    asm volatile("mbarrier.arrive.shared.b64 _, [%0];" :: "r"(addr) : "memory")
// .noinc is REQUIRED: the default form is self-balancing and never completes.
#define CP_MBAR_ARRIVE(addr) \
    asm volatile("cp.async.mbarrier.arrive.noinc.shared.b64 [%0];" :: "r"(addr) : "memory")

__device__ __forceinline__ void mbar_wait(uint32_t mbar, uint32_t parity) {
    asm volatile(
        "{\n\t.reg .pred P;\n\t"
        "LW_%=:\n\t"
        "mbarrier.try_wait.parity.acquire.cta.shared::cta.b64 P, [%0], %1, 0x989680;\n\t"
        "@P bra.uni LD_%=;\n\t"
        "bra.uni LW_%=;\n\t"
        "LD_%=:\n\t}"
        :: "r"(mbar), "r"(parity) : "memory");
}
// producer-side wait: post-wait writes are async-proxy (cp.async) only
__device__ __forceinline__ void mbar_wait_relaxed(uint32_t mbar, uint32_t parity) {
    asm volatile(
        "{\n\t.reg .pred P;\n\t"
        "LW_%=:\n\t"
        "mbarrier.try_wait.parity.relaxed.cta.shared::cta.b64 P, [%0], %1, 0x989680;\n\t"
        "@P bra.uni LD_%=;\n\t"
        "bra.uni LW_%=;\n\t"
        "LD_%=:\n\t}"
        :: "r"(mbar), "r"(parity) : "memory");
}

__device__ __forceinline__ void ldsm4(uint32_t* d, uint32_t a) {
    asm volatile("ldmatrix.sync.aligned.m8n8.x4.shared.b16 {%0,%1,%2,%3}, [%4];"
        : "=r"(d[0]), "=r"(d[1]), "=r"(d[2]), "=r"(d[3]) : "r"(a));
}
__device__ __forceinline__ void mma16(float* c, const uint32_t* a, const uint32_t* b) {
    asm volatile("mma.sync.aligned.m16n8k16.row.col.f32.f16.f16.f32 "
        "{%0,%1,%2,%3}, {%4,%5,%6,%7}, {%8,%9}, {%0,%1,%2,%3};"
        : "+f"(c[0]), "+f"(c[1]), "+f"(c[2]), "+f"(c[3])
        : "r"(a[0]), "r"(a[1]), "r"(a[2]), "r"(a[3]), "r"(b[0]), "r"(b[1]));
}
__device__ __forceinline__ float sigm(float x) {
    return __fdividef(1.f, 1.f + __expf(-x));
}

// ============================ merged fp32 -> fp16 convert ==================
// One launch converts X, W1, W3 (range-branched; all memory-bound).
__global__ void cvt_all_kernel(const float4* __restrict__ x,
                               const float4* __restrict__ w1,
                               const float4* __restrict__ w3,
                               uint2* __restrict__ xh,
                               uint2* __restrict__ w1h,
                               uint2* __restrict__ w3h) {
    int i = blockIdx.x * blockDim.x + threadIdx.x;
    const float4* s;
    uint2* d;
    int idx;
    if (i < N4_X)                { s = x;  d = xh;  idx = i; }
    else if (i < N4_X + N4_W1)   { s = w1; d = w1h; idx = i - N4_X; }
    else if (i < N4_ALL)         { s = w3; d = w3h; idx = i - N4_X - N4_W1; }
    else return;
    float4 v = s[idx];
    __half2 h0 = __floats2half2_rn(v.x, v.y);
    __half2 h1 = __floats2half2_rn(v.z, v.w);
    uint2 o;
    o.x = *(uint32_t*)&h0;
    o.y = *(uint32_t*)&h1;
    d[idx] = o;
}

// ============================ stage load ===================================
// smem element (row r, k): byte = r*128 + (((k>>3) ^ (r&7))<<4) + (k&7)*2
template<int KDIM>
__device__ __forceinline__ void stage_load(
    const __half* __restrict__ A, const __half* __restrict__ B,
    int m0, int n0, int kc, int s, uint32_t sb, int tid)
{
    const uint32_t so = sb + (uint32_t)(s * STAGE_B);
    #pragma unroll
    for (int i = 0; i < 8; ++i) {                 // A: 128 rows x 8 x 16B
        int id = tid + i * NTHR;
        int r = id >> 3, u = id & 7;
        cpa16(so + r * 128 + ((u ^ (r & 7)) << 4),
              A + (size_t)(m0 + r) * KDIM + kc * BK + u * 8);
    }
    #pragma unroll
    for (int i = 0; i < 8; ++i) {                 // B: 128 rows x 8 x 16B
        int id = tid + i * NTHR;
        int r = id >> 3, u = id & 7;
        cpa16(so + B_OFF + r * 128 + ((u ^ (r & 7)) << 4),
              B + (size_t)(n0 + r) * KDIM + kc * BK + u * 8);
    }
}

// ============================ fc1: R9 mbarrier pipeline (best measured) ====
// full[s]: 128 .noinc cp-completion arrivals; empty[s]: 4 warp arrivals.
// Warps track private (stage, parity) cursors -> no CTA-wide rendezvous in
// the k-loop; skew is absorbed by the ring instead of serialized.
__global__ void __launch_bounds__(NTHR, 2) fc1_kernel(
    const __half* __restrict__ X,  const __half* __restrict__ W1,
    const float* __restrict__ b1,  const float* __restrict__ W2,
    const float* __restrict__ b2,  __half* __restrict__ x2)
{
    extern __shared__ float sm[];
    const uint32_t sb = sm32(sm);
    const int tid = threadIdx.x, lane = tid & 31, wid = tid >> 5;
    const int wm = wid >> 1, wn = wid & 1;
    const int m0 = blockIdx.y * BM, n0 = blockIdx.x * BN;
    const uint32_t mbf = sb + MB_OFF;              // full[3]
    const uint32_t mbe = sb + MB_OFF + 24;         // empty[3]

    if (tid == 0) {
        #pragma unroll
        for (int s = 0; s < NSTG; ++s) {
            MBAR_INIT(mbf + 8 * s, NTHR);          // 128 .noinc cp-arrives
            MBAR_INIT(mbe + 8 * s, 4);             // one arrive per warp
        }
    }
    __syncthreads();

    const int lr = lane & 7, j = lane >> 3;
    const int jlow = j & 1, jhi = j >> 1;
    uint32_t baseA[4], baseB[4];
    #pragma unroll
    for (int mt = 0; mt < 4; ++mt)
        baseA[mt] = (uint32_t)((wm * 64 + mt * 16 + (jlow << 3) + lr) * 128);
    #pragma unroll
    for (int p = 0; p < 4; ++p)
        baseB[p] = (uint32_t)(B_OFF + (wn * 64 + (2 * p + jhi) * 8 + lr) * 128);

    float acc[4][8][4];
    #pragma unroll
    for (int i = 0; i < 4; ++i)
        #pragma unroll
        for (int j2 = 0; j2 < 8; ++j2)
            #pragma unroll
            for (int k = 0; k < 4; ++k) acc[i][j2][k] = 0.f;

    // ---- prologue: fill stages 0,1 ----
    stage_load<D_IN>(X, W1, m0, n0, 0, 0, sb, tid);
    CP_MBAR_ARRIVE(mbf + 0);
    stage_load<D_IN>(X, W1, m0, n0, 1, 1, sb, tid);
    CP_MBAR_ARRIVE(mbf + 8);

    int lc = 2;                                    // next chunk to load
    #pragma unroll 1
    for (int c = 0; c < NC1; ++c) {
        // ---- load-ahead chunk lc ----
        if (lc < NC1) {
            const int lf = lc / NSTG;              // fill round
            const int lss = lc - lf * NSTG;        // its stage
            if (lc >= NSTG) mbar_wait(mbe + 8 * lss, (uint32_t)((lf - 1) & 1));
            stage_load<D_IN>(X, W1, m0, n0, lc, lss, sb, tid);
            CP_MBAR_ARRIVE(mbf + 8 * lss);
            ++lc;
        }

        // ---- consume chunk c ----
        const int cf = c / NSTG;
        const int cs = c - cf * NSTG;
        mbar_wait(mbf + 8 * cs, (uint32_t)(cf & 1));

        const uint32_t stg = sb + (uint32_t)cs * STAGE_B;
        #pragma unroll
        for (int ks = 0; ks < 4; ++ks) {
            const uint32_t swzA = (uint32_t)(((2 * ks + jhi) ^ lr) << 4);
            const uint32_t swzB = (uint32_t)(((2 * ks + jlow) ^ lr) << 4);
            uint32_t a[4][4], b[4][4];
            #pragma unroll
            for (int mt = 0; mt < 4; ++mt) ldsm4(a[mt], stg + baseA[mt] + swzA);
            #pragma unroll
            for (int p = 0; p < 4; ++p)    ldsm4(b[p],  stg + baseB[p] + swzB);
            #pragma unroll
            for (int mt = 0; mt < 4; ++mt) {
                #pragma unroll
                for (int p = 0; p < 4; ++p) {
                    mma16(acc[mt][2 * p],     a[mt], &b[p][0]);
                    mma16(acc[mt][2 * p + 1], a[mt], &b[p][2]);
                }
            }
        }
        __syncwarp();
        if (lane == 0) MBAR_ARRIVE(mbe + 8 * cs);  // warp done with stage cs
    }

    // -------- fused epilogue: bias+sigmoid -> grouped dot (quad shfl) ------
    const int q = lane & 3, g2 = lane >> 2;
    const int ntile = blockIdx.x;
    float* es = sm + ES_OFF / 4;                   // dedicated buffer

    float b1v[16], w2v[16];
    #pragma unroll
    for (int nt = 0; nt < 8; ++nt) {
        int cidx = n0 + wn * 64 + nt * 8 + 2 * q;
        b1v[2 * nt]     = __ldg(b1 + cidx);
        b1v[2 * nt + 1] = __ldg(b1 + cidx + 1);
        w2v[2 * nt]     = __ldg(W2 + cidx);
        w2v[2 * nt + 1] = __ldg(W2 + cidx + 1);
    }
    const float b2v0 = __ldg(b2 + ntile * 16 + wn * 8 + q);
    const float b2v1 = __ldg(b2 + ntile * 16 + wn * 8 + q + 4);

    #pragma unroll
    for (int mt = 0; mt < 4; ++mt) {
        #pragma unroll
        for (int nt = 0; nt < 8; ++nt) {
            float h00 = sigm(acc[mt][nt][0] + b1v[2 * nt]);
            float h01 = sigm(acc[mt][nt][1] + b1v[2 * nt + 1]);
            float h10 = sigm(acc[mt][nt][2] + b1v[2 * nt]);
            float h11 = sigm(acc[mt][nt][3] + b1v[2 * nt + 1]);
            float p0 = h00 * w2v[2 * nt] + h01 * w2v[2 * nt + 1];
            float p1 = h10 * w2v[2 * nt] + h11 * w2v[2 * nt + 1];
            p0 += __shfl_xor_sync(0xffffffffu, p0, 1);
            p0 += __shfl_xor_sync(0xffffffffu, p0, 2);
            p1 += __shfl_xor_sync(0xffffffffu, p1, 1);
            p1 += __shfl_xor_sync(0xffffffffu, p1, 2);
            if (q == (nt & 3)) {
                int g  = wn * 8 + nt;              // 16 groups per CTA
                int r0 = wm * 64 + mt * 16 + g2;
                float bv = (nt < 4) ? b2v0 : b2v1;
                es[r0 * 20 + g]       = sigm(p0 + bv);
                es[(r0 + 8) * 20 + g] = sigm(p1 + bv);
            }
        }
    }
    __syncthreads();

    // coalesced fp16 store: 128 rows x 16 groups; 1 thread per row
    {
        const float* e = es + tid * 20;
        __half2 h0 = __floats2half2_rn(e[0],  e[1]);
        __half2 h1 = __floats2half2_rn(e[2],  e[3]);
        __half2 h2 = __floats2half2_rn(e[4],  e[5]);
        __half2 h3 = __floats2half2_rn(e[6],  e[7]);
        __half2 h4 = __floats2half2_rn(e[8],  e[9]);
        __half2 h5 = __floats2half2_rn(e[10], e[11]);
        __half2 h6 = __floats2half2_rn(e[12], e[13]);
        __half2 h7 = __floats2half2_rn(e[14], e[15]);
        uint4 o0, o1;
        o0.x = *(uint32_t*)&h0; o0.y = *(uint32_t*)&h1;
        o0.z = *(uint32_t*)&h2; o0.w = *(uint32_t*)&h3;
        o1.x = *(uint32_t*)&h4; o1.y = *(uint32_t*)&h5;
        o1.z = *(uint32_t*)&h6; o1.w = *(uint32_t*)&h7;
        __half* dst = x2 + (size_t)(m0 + tid) * NH2 + ntile * 16;
        *(uint4*)dst       = o0;
        *(uint4*)(dst + 8) = o1;
    }
}

// ============================ fc3: mbar pipeline (R10, measured better) ====
__global__ void __launch_bounds__(NTHR, 2) fc3_kernel(
    const __half* __restrict__ A,  const __half* __restrict__ W3,
    const float* __restrict__ b3,  float* __restrict__ out)
{
    extern __shared__ float sm[];
    const uint32_t sb = sm32(sm);
    const int tid = threadIdx.x, lane = tid & 31, wid = tid >> 5;
    const int wm = wid >> 1, wn = wid & 1;
    const int m0 = blockIdx.y * BM, n0 = blockIdx.x * BN;
    const uint32_t mbf = sb + MB3_OFF;
    const uint32_t mbe = sb + MB3_OFF + 24;

    if (tid == 0) {
        #pragma unroll
        for (int s = 0; s < NSTG; ++s) {
            MBAR_INIT(mbf + 8 * s, NTHR);
            MBAR_INIT(mbe + 8 * s, 4);
        }
    }
    __syncthreads();

    const int lr = lane & 7, j = lane >> 3;
    const int jlow = j & 1, jhi = j >> 1;
    uint32_t baseA[4], baseB[4];
    #pragma unroll
    for (int mt = 0; mt < 4; ++mt)
        baseA[mt] = (uint32_t)((wm * 64 + mt * 16 + (jlow << 3) + lr) * 128);
    #pragma unroll
    for (int p = 0; p < 4; ++p)
        baseB[p] = (uint32_t)(B_OFF + (wn * 64 + (2 * p + jhi) * 8 + lr) * 128);

    float acc[4][8][4];
    #pragma unroll
    for (int i = 0; i < 4; ++i)
        #pragma unroll
        for (int j2 = 0; j2 < 8; ++j2)
            #pragma unroll
            for (int k = 0; k < 4; ++k) acc[i][j2][k] = 0.f;

    auto do_ks = [&](uint32_t stg, int kse) {
        const uint32_t swzA = (uint32_t)(((2 * kse + jhi) ^ lr) << 4);
        const uint32_t swzB = (uint32_t)(((2 * kse + jlow) ^ lr) << 4);
        uint32_t a[4][4], b[4][4];
        #pragma unroll
        for (int mt = 0; mt < 4; ++mt) ldsm4(a[mt], stg + baseA[mt] + swzA);
        #pragma unroll
        for (int p = 0; p < 4; ++p)    ldsm4(b[p],  stg + baseB[p] + swzB);
        #pragma unroll
        for (int mt = 0; mt < 4; ++mt) {
            #pragma unroll
            for (int p = 0; p < 4; ++p) {
                mma16(acc[mt][2 * p],     a[mt], &b[p][0]);
                mma16(acc[mt][2 * p + 1], a[mt], &b[p][2]);
            }
        }
    };

    stage_load<NH2>(A, W3, m0, n0, 0, 0, sb, tid);
    CP_MBAR_ARRIVE(mbf + 0);
    stage_load<NH2>(A, W3, m0, n0, 1, 1, sb, tid);
    CP_MBAR_ARRIVE(mbf + 8);

    int lc = 2;
    #pragma unroll 1
    for (int c = 0; c < NC3; ++c) {
        const int cf = c / NSTG;
        const int cs = c - cf * NSTG;
        mbar_wait(mbf + 8 * cs, (uint32_t)(cf & 1));
        const uint32_t stg = sb + (uint32_t)cs * STAGE_B;

        do_ks(stg, wid & 3);
        if (lc < NC3) {
            const int lf = lc / NSTG;
            const int lss = lc - lf * NSTG;
            if (lc >= NSTG) mbar_wait_relaxed(mbe + 8 * lss, (uint32_t)((lf - 1) & 1));
            stage_load<NH2>(A, W3, m0, n0, lc, lss, sb, tid);
            CP_MBAR_ARRIVE(mbf + 8 * lss);
            ++lc;
        }
        do_ks(stg, (wid + 1) & 3);
        do_ks(stg, (wid + 2) & 3);
        do_ks(stg, (wid + 3) & 3);

        __syncwarp();
        if (lane == 0) MBAR_ARRIVE(mbe + 8 * cs);
    }

    const int q = lane & 3, g2 = lane >> 2;
    #pragma unroll
    for (int mt = 0; mt < 4; ++mt) {
        #pragma unroll
        for (int nt = 0; nt < 8; ++nt) {
            int cl = wn * 64 + nt * 8 + 2 * q;
            int r0 = m0 + wm * 64 + mt * 16 + g2;
            float bb0 = __ldg(b3 + n0 + cl);
            float bb1 = __ldg(b3 + n0 + cl + 1);
            float2 v0 = make_float2(acc[mt][nt][0] + bb0, acc[mt][nt][1] + bb1);
            float2 v1 = make_float2(acc[mt][nt][2] + bb0, acc[mt][nt][3] + bb1);
            *(float2*)(out + (size_t)r0 * D_OUT + n0 + cl)       = v0;
            *(float2*)(out + (size_t)(r0 + 8) * D_OUT + n0 + cl) = v1;
        }
    }
}

// ============================ host =========================================
extern "C" void kernel_launch(void* const* d_in, const int* in_sizes, int n_in,
                              void* d_out, int out_size) {
    (void)in_sizes; (void)n_in; (void)out_size;
    const float* x  = (const float*)d_in[0];
    const float* W1 = (const float*)d_in[1];
    const float* b1 = (const float*)d_in[2];
    const float* W2 = (const float*)d_in[3];
    const float* b2 = (const float*)d_in[4];
    const float* W3 = (const float*)d_in[5];
    const float* b3 = (const float*)d_in[6];
    float* out = (float*)d_out;

    void *pXh = nullptr, *pW1h = nullptr, *pW3h = nullptr, *px2h = nullptr;
    cudaGetSymbolAddress(&pXh,  g_Xh);
    cudaGetSymbolAddress(&pW1h, g_W1h);
    cudaGetSymbolAddress(&pW3h, g_W3h);
    cudaGetSymbolAddress(&px2h, g_x2h);

    const int smem1 = MB_OFF + 64;                    // 108608 B
    const int smem3 = MB3_OFF + 64;                   //  98368 B
    cudaFuncSetAttribute(fc1_kernel, cudaFuncAttributeMaxDynamicSharedMemorySize, smem1);
    cudaFuncSetAttribute(fc3_kernel, cudaFuncAttributeMaxDynamicSharedMemorySize, smem3);

    // single merged convert launch (X, W1, W3 -> fp16)
    cvt_all_kernel<<<(N4_ALL + 255) / 256, 256>>>(
        (const float4*)x, (const float4*)W1, (const float4*)W3,
        (uint2*)pXh, (uint2*)pW1h, (uint2*)pW3h);

    fc1_kernel<<<dim3(NH1 / BN, NROWS / BM), NTHR, smem1>>>(
        (const __half*)pXh, (const __half*)pW1h, b1, W2, b2, (__half*)px2h);
    fc3_kernel<<<dim3(D_OUT / BN, NROWS / BM), NTHR, smem3>>>(
        (const __half*)px2h, (const __half*)pW3h, b3, out);
}

// round 12
// speedup vs baseline: 1.0385x; 1.0095x over previous
#include <cuda_runtime.h>
#include <cuda_fp16.h>
#include <cstdint>
#include <cstddef>

// ============================ problem constants ============================
#define D_IN   1024
#define NH1    4096
#define NH2    512
#define D_OUT  256
#define NROWS  16384

// ============================ tiling =======================================
#define BM 128
#define BN 128
#define BK 64                        // fp16: row = 128B
#define NSTG 3
#define STAGE_B 32768                // (BM+BN)*BK*2 bytes
#define B_OFF   16384                // B tile offset within a stage
#define NTHR 128                     // 4 warps, warp tile 64x64
#define NC1  (D_IN / BK)             // 16 k-chunks (fc1)
#define NC3  (NH2 / BK)              // 8 k-chunks (fc3)
#define ES_OFF 98304                 // epilogue buffer (3 stages end)
#define MB_OFF 108544                // fc1 mbarriers: full[3] then empty[3]
#define MB3_OFF 98304                // fc3 mbarriers

// cvt segment sizes (in float4 units); all multiples of 512
#define N4_X  (NROWS * D_IN / 4)     // 4194304
#define N4_W1 (NH1 * D_IN / 4)       // 1048576
#define N4_W3 (D_OUT * NH2 / 4)      // 32768
#define N4_ALL (N4_X + N4_W1 + N4_W3)
#define CVT_BLK_F4 512               // float4 per block (256 thr x 2)

// ============================ scratch ======================================
__device__ __align__(1024) __half g_Xh [NROWS * D_IN];
__device__ __align__(1024) __half g_W1h[NH1 * D_IN];
__device__ __align__(1024) __half g_W3h[D_OUT * NH2];
__device__ __align__(1024) __half g_x2h[NROWS * NH2];

// ============================ device helpers ===============================
__device__ __forceinline__ uint32_t sm32(const void* p) {
    uint32_t a;
    asm("{ .reg .u64 t; cvta.to.shared.u64 t, %1; cvt.u32.u64 %0, t; }"
        : "=r"(a) : "l"(p));
    return a;
}
__device__ __forceinline__ void cpa16(uint32_t d, const void* s) {
    asm volatile("cp.async.cg.shared.global [%0], [%1], 16;" :: "r"(d), "l"(s));
}

#define MBAR_INIT(addr, cnt) \
    asm volatile("mbarrier.init.shared.b64 [%0], %1;" :: "r"(addr), "r"(cnt) : "memory")
#define MBAR_ARRIVE(addr) \
    asm volatile("mbarrier.arrive.shared.b64 _, [%0];" :: "r"(addr) : "memory")
// .noinc is REQUIRED: the default form is self-balancing and never completes.
#define CP_MBAR_ARRIVE(addr) \
    asm volatile("cp.async.mbarrier.arrive.noinc.shared.b64 [%0];" :: "r"(addr) : "memory")

__device__ __forceinline__ void mbar_wait(uint32_t mbar, uint32_t parity) {
    asm volatile(
        "{\n\t.reg .pred P;\n\t"
        "LW_%=:\n\t"
        "mbarrier.try_wait.parity.acquire.cta.shared::cta.b64 P, [%0], %1, 0x989680;\n\t"
        "@P bra.uni LD_%=;\n\t"
        "bra.uni LW_%=;\n\t"
        "LD_%=:\n\t}"
        :: "r"(mbar), "r"(parity) : "memory");
}
// producer-side wait: post-wait writes are async-proxy (cp.async) only
__device__ __forceinline__ void mbar_wait_relaxed(uint32_t mbar, uint32_t parity) {
    asm volatile(
        "{\n\t.reg .pred P;\n\t"
        "LW_%=:\n\t"
        "mbarrier.try_wait.parity.relaxed.cta.shared::cta.b64 P, [%0], %1, 0x989680;\n\t"
        "@P bra.uni LD_%=;\n\t"
        "bra.uni LW_%=;\n\t"
        "LD_%=:\n\t}"
        :: "r"(mbar), "r"(parity) : "memory");
}

__device__ __forceinline__ void ldsm4(uint32_t* d, uint32_t a) {
    asm volatile("ldmatrix.sync.aligned.m8n8.x4.shared.b16 {%0,%1,%2,%3}, [%4];"
        : "=r"(d[0]), "=r"(d[1]), "=r"(d[2]), "=r"(d[3]) : "r"(a));
}
__device__ __forceinline__ void mma16(float* c, const uint32_t* a, const uint32_t* b) {
    asm volatile("mma.sync.aligned.m16n8k16.row.col.f32.f16.f16.f32 "
        "{%0,%1,%2,%3}, {%4,%5,%6,%7}, {%8,%9}, {%0,%1,%2,%3};"
        : "+f"(c[0]), "+f"(c[1]), "+f"(c[2]), "+f"(c[3])
        : "r"(a[0]), "r"(a[1]), "r"(a[2]), "r"(a[3]), "r"(b[0]), "r"(b[1]));
}
__device__ __forceinline__ float sigm(float x) {
    return __fdividef(1.f, 1.f + __expf(-x));
}

// ============================ merged fp32 -> fp16 convert ==================
// One launch; 512 float4 per block (2 per thread, independent -> MLP=2).
// Segment sizes are multiples of 512, so each block maps to exactly one
// segment: the three-way branch is block-uniform.
__global__ void __launch_bounds__(256) cvt_all_kernel(
    const float4* __restrict__ x,
    const float4* __restrict__ w1,
    const float4* __restrict__ w3,
    uint2* __restrict__ xh,
    uint2* __restrict__ w1h,
    uint2* __restrict__ w3h)
{
    const int base = blockIdx.x * CVT_BLK_F4;
    const float4* s;
    uint2* d;
    int off;
    if (base < N4_X)              { s = x;  d = xh;  off = base; }
    else if (base < N4_X + N4_W1) { s = w1; d = w1h; off = base - N4_X; }
    else                          { s = w3; d = w3h; off = base - N4_X - N4_W1; }

    const int i0 = off + threadIdx.x;
    const int i1 = i0 + 256;
    float4 v0 = s[i0];                 // two independent loads in flight
    float4 v1 = s[i1];

    __half2 a0 = __floats2half2_rn(v0.x, v0.y);
    __half2 a1 = __floats2half2_rn(v0.z, v0.w);
    uint2 o0;
    o0.x = *(uint32_t*)&a0; o0.y = *(uint32_t*)&a1;
    d[i0] = o0;

    __half2 b0 = __floats2half2_rn(v1.x, v1.y);
    __half2 b1 = __floats2half2_rn(v1.z, v1.w);
    uint2 o1;
    o1.x = *(uint32_t*)&b0; o1.y = *(uint32_t*)&b1;
    d[i1] = o1;
}

// ============================ stage load ===================================
// smem element (row r, k): byte = r*128 + (((k>>3) ^ (r&7))<<4) + (k&7)*2
template<int KDIM>
__device__ __forceinline__ void stage_load(
    const __half* __restrict__ A, const __half* __restrict__ B,
    int m0, int n0, int kc, int s, uint32_t sb, int tid)
{
    const uint32_t so = sb + (uint32_t)(s * STAGE_B);
    #pragma unroll
    for (int i = 0; i < 8; ++i) {                 // A: 128 rows x 8 x 16B
        int id = tid + i * NTHR;
        int r = id >> 3, u = id & 7;
        cpa16(so + r * 128 + ((u ^ (r & 7)) << 4),
              A + (size_t)(m0 + r) * KDIM + kc * BK + u * 8);
    }
    #pragma unroll
    for (int i = 0; i < 8; ++i) {                 // B: 128 rows x 8 x 16B
        int id = tid + i * NTHR;
        int r = id >> 3, u = id & 7;
        cpa16(so + B_OFF + r * 128 + ((u ^ (r & 7)) << 4),
              B + (size_t)(n0 + r) * KDIM + kc * BK + u * 8);
    }
}

// ============================ fc1: R9 mbarrier pipeline (best measured) ====
// full[s]: 128 .noinc cp-completion arrivals; empty[s]: 4 warp arrivals.
// Warps track private (stage, parity) cursors -> no CTA-wide rendezvous in
// the k-loop; skew is absorbed by the ring instead of serialized.
__global__ void __launch_bounds__(NTHR, 2) fc1_kernel(
    const __half* __restrict__ X,  const __half* __restrict__ W1,
    const float* __restrict__ b1,  const float* __restrict__ W2,
    const float* __restrict__ b2,  __half* __restrict__ x2)
{
    extern __shared__ float sm[];
    const uint32_t sb = sm32(sm);
    const int tid = threadIdx.x, lane = tid & 31, wid = tid >> 5;
    const int wm = wid >> 1, wn = wid & 1;
    const int m0 = blockIdx.y * BM, n0 = blockIdx.x * BN;
    const uint32_t mbf = sb + MB_OFF;              // full[3]
    const uint32_t mbe = sb + MB_OFF + 24;         // empty[3]

    if (tid == 0) {
        #pragma unroll
        for (int s = 0; s < NSTG; ++s) {
            MBAR_INIT(mbf + 8 * s, NTHR);          // 128 .noinc cp-arrives
            MBAR_INIT(mbe + 8 * s, 4);             // one arrive per warp
        }
    }
    __syncthreads();

    const int lr = lane & 7, j = lane >> 3;
    const int jlow = j & 1, jhi = j >> 1;
    uint32_t baseA[4], baseB[4];
    #pragma unroll
    for (int mt = 0; mt < 4; ++mt)
        baseA[mt] = (uint32_t)((wm * 64 + mt * 16 + (jlow << 3) + lr) * 128);
    #pragma unroll
    for (int p = 0; p < 4; ++p)
        baseB[p] = (uint32_t)(B_OFF + (wn * 64 + (2 * p + jhi) * 8 + lr) * 128);

    float acc[4][8][4];
    #pragma unroll
    for (int i = 0; i < 4; ++i)
        #pragma unroll
        for (int j2 = 0; j2 < 8; ++j2)
            #pragma unroll
            for (int k = 0; k < 4; ++k) acc[i][j2][k] = 0.f;

    // ---- prologue: fill stages 0,1 ----
    stage_load<D_IN>(X, W1, m0, n0, 0, 0, sb, tid);
    CP_MBAR_ARRIVE(mbf + 0);
    stage_load<D_IN>(X, W1, m0, n0, 1, 1, sb, tid);
    CP_MBAR_ARRIVE(mbf + 8);

    int lc = 2;                                    // next chunk to load
    #pragma unroll 1
    for (int c = 0; c < NC1; ++c) {
        // ---- load-ahead chunk lc ----
        if (lc < NC1) {
            const int lf = lc / NSTG;              // fill round
            const int lss = lc - lf * NSTG;        // its stage
            if (lc >= NSTG) mbar_wait(mbe + 8 * lss, (uint32_t)((lf - 1) & 1));
            stage_load<D_IN>(X, W1, m0, n0, lc, lss, sb, tid);
            CP_MBAR_ARRIVE(mbf + 8 * lss);
            ++lc;
        }

        // ---- consume chunk c ----
        const int cf = c / NSTG;
        const int cs = c - cf * NSTG;
        mbar_wait(mbf + 8 * cs, (uint32_t)(cf & 1));

        const uint32_t stg = sb + (uint32_t)cs * STAGE_B;
        #pragma unroll
        for (int ks = 0; ks < 4; ++ks) {
            const uint32_t swzA = (uint32_t)(((2 * ks + jhi) ^ lr) << 4);
            const uint32_t swzB = (uint32_t)(((2 * ks + jlow) ^ lr) << 4);
            uint32_t a[4][4], b[4][4];
            #pragma unroll
            for (int mt = 0; mt < 4; ++mt) ldsm4(a[mt], stg + baseA[mt] + swzA);
            #pragma unroll
            for (int p = 0; p < 4; ++p)    ldsm4(b[p],  stg + baseB[p] + swzB);
            #pragma unroll
            for (int mt = 0; mt < 4; ++mt) {
                #pragma unroll
                for (int p = 0; p < 4; ++p) {
                    mma16(acc[mt][2 * p],     a[mt], &b[p][0]);
                    mma16(acc[mt][2 * p + 1], a[mt], &b[p][2]);
                }
            }
        }
        __syncwarp();
        if (lane == 0) MBAR_ARRIVE(mbe + 8 * cs);  // warp done with stage cs
    }

    // -------- fused epilogue: bias+sigmoid -> grouped dot (quad shfl) ------
    const int q = lane & 3, g2 = lane >> 2;
    const int ntile = blockIdx.x;
    float* es = sm + ES_OFF / 4;                   // dedicated buffer

    float b1v[16], w2v[16];
    #pragma unroll
    for (int nt = 0; nt < 8; ++nt) {
        int cidx = n0 + wn * 64 + nt * 8 + 2 * q;
        b1v[2 * nt]     = __ldg(b1 + cidx);
        b1v[2 * nt + 1] = __ldg(b1 + cidx + 1);
        w2v[2 * nt]     = __ldg(W2 + cidx);
        w2v[2 * nt + 1] = __ldg(W2 + cidx + 1);
    }
    const float b2v0 = __ldg(b2 + ntile * 16 + wn * 8 + q);
    const float b2v1 = __ldg(b2 + ntile * 16 + wn * 8 + q + 4);

    #pragma unroll
    for (int mt = 0; mt < 4; ++mt) {
        #pragma unroll
        for (int nt = 0; nt < 8; ++nt) {
            float h00 = sigm(acc[mt][nt][0] + b1v[2 * nt]);
            float h01 = sigm(acc[mt][nt][1] + b1v[2 * nt + 1]);
            float h10 = sigm(acc[mt][nt][2] + b1v[2 * nt]);
            float h11 = sigm(acc[mt][nt][3] + b1v[2 * nt + 1]);
            float p0 = h00 * w2v[2 * nt] + h01 * w2v[2 * nt + 1];
            float p1 = h10 * w2v[2 * nt] + h11 * w2v[2 * nt + 1];
            p0 += __shfl_xor_sync(0xffffffffu, p0, 1);
            p0 += __shfl_xor_sync(0xffffffffu, p0, 2);
            p1 += __shfl_xor_sync(0xffffffffu, p1, 1);
            p1 += __shfl_xor_sync(0xffffffffu, p1, 2);
            if (q == (nt & 3)) {
                int g  = wn * 8 + nt;              // 16 groups per CTA
                int r0 = wm * 64 + mt * 16 + g2;
                float bv = (nt < 4) ? b2v0 : b2v1;
                es[r0 * 20 + g]       = sigm(p0 + bv);
                es[(r0 + 8) * 20 + g] = sigm(p1 + bv);
            }
        }
    }
    __syncthreads();

    // coalesced fp16 store: 128 rows x 16 groups; 1 thread per row
    {
        const float* e = es + tid * 20;
        __half2 h0 = __floats2half2_rn(e[0],  e[1]);
        __half2 h1 = __floats2half2_rn(e[2],  e[3]);
        __half2 h2 = __floats2half2_rn(e[4],  e[5]);
        __half2 h3 = __floats2half2_rn(e[6],  e[7]);
        __half2 h4 = __floats2half2_rn(e[8],  e[9]);
        __half2 h5 = __floats2half2_rn(e[10], e[11]);
        __half2 h6 = __floats2half2_rn(e[12], e[13]);
        __half2 h7 = __floats2half2_rn(e[14], e[15]);
        uint4 o0, o1;
        o0.x = *(uint32_t*)&h0; o0.y = *(uint32_t*)&h1;
        o0.z = *(uint32_t*)&h2; o0.w = *(uint32_t*)&h3;
        o1.x = *(uint32_t*)&h4; o1.y = *(uint32_t*)&h5;
        o1.z = *(uint32_t*)&h6; o1.w = *(uint32_t*)&h7;
        __half* dst = x2 + (size_t)(m0 + tid) * NH2 + ntile * 16;
        *(uint4*)dst       = o0;
        *(uint4*)(dst + 8) = o1;
    }
}

// ============================ fc3: mbar pipeline (R10, measured better) ====
__global__ void __launch_bounds__(NTHR, 2) fc3_kernel(
    const __half* __restrict__ A,  const __half* __restrict__ W3,
    const float* __restrict__ b3,  float* __restrict__ out)
{
    extern __shared__ float sm[];
    const uint32_t sb = sm32(sm);
    const int tid = threadIdx.x, lane = tid & 31, wid = tid >> 5;
    const int wm = wid >> 1, wn = wid & 1;
    const int m0 = blockIdx.y * BM, n0 = blockIdx.x * BN;
    const uint32_t mbf = sb + MB3_OFF;
    const uint32_t mbe = sb + MB3_OFF + 24;

    if (tid == 0) {
        #pragma unroll
        for (int s = 0; s < NSTG; ++s) {
            MBAR_INIT(mbf + 8 * s, NTHR);
            MBAR_INIT(mbe + 8 * s, 4);
        }
    }
    __syncthreads();

    const int lr = lane & 7, j = lane >> 3;
    const int jlow = j & 1, jhi = j >> 1;
    uint32_t baseA[4], baseB[4];
    #pragma unroll
    for (int mt = 0; mt < 4; ++mt)
        baseA[mt] = (uint32_t)((wm * 64 + mt * 16 + (jlow << 3) + lr) * 128);
    #pragma unroll
    for (int p = 0; p < 4; ++p)
        baseB[p] = (uint32_t)(B_OFF + (wn * 64 + (2 * p + jhi) * 8 + lr) * 128);

    float acc[4][8][4];
    #pragma unroll
    for (int i = 0; i < 4; ++i)
        #pragma unroll
        for (int j2 = 0; j2 < 8; ++j2)
            #pragma unroll
            for (int k = 0; k < 4; ++k) acc[i][j2][k] = 0.f;

    auto do_ks = [&](uint32_t stg, int kse) {
        const uint32_t swzA = (uint32_t)(((2 * kse + jhi) ^ lr) << 4);
        const uint32_t swzB = (uint32_t)(((2 * kse + jlow) ^ lr) << 4);
        uint32_t a[4][4], b[4][4];
        #pragma unroll
        for (int mt = 0; mt < 4; ++mt) ldsm4(a[mt], stg + baseA[mt] + swzA);
        #pragma unroll
        for (int p = 0; p < 4; ++p)    ldsm4(b[p],  stg + baseB[p] + swzB);
        #pragma unroll
        for (int mt = 0; mt < 4; ++mt) {
            #pragma unroll
            for (int p = 0; p < 4; ++p) {
                mma16(acc[mt][2 * p],     a[mt], &b[p][0]);
                mma16(acc[mt][2 * p + 1], a[mt], &b[p][2]);
            }
        }
    };

    stage_load<NH2>(A, W3, m0, n0, 0, 0, sb, tid);
    CP_MBAR_ARRIVE(mbf + 0);
    stage_load<NH2>(A, W3, m0, n0, 1, 1, sb, tid);
    CP_MBAR_ARRIVE(mbf + 8);

    int lc = 2;
    #pragma unroll 1
    for (int c = 0; c < NC3; ++c) {
        const int cf = c / NSTG;
        const int cs = c - cf * NSTG;
        mbar_wait(mbf + 8 * cs, (uint32_t)(cf & 1));
        const uint32_t stg = sb + (uint32_t)cs * STAGE_B;

        do_ks(stg, wid & 3);
        if (lc < NC3) {
            const int lf = lc / NSTG;
            const int lss = lc - lf * NSTG;
            if (lc >= NSTG) mbar_wait_relaxed(mbe + 8 * lss, (uint32_t)((lf - 1) & 1));
            stage_load<NH2>(A, W3, m0, n0, lc, lss, sb, tid);
            CP_MBAR_ARRIVE(mbf + 8 * lss);
            ++lc;
        }
        do_ks(stg, (wid + 1) & 3);
        do_ks(stg, (wid + 2) & 3);
        do_ks(stg, (wid + 3) & 3);

        __syncwarp();
        if (lane == 0) MBAR_ARRIVE(mbe + 8 * cs);
    }

    const int q = lane & 3, g2 = lane >> 2;
    #pragma unroll
    for (int mt = 0; mt < 4; ++mt) {
        #pragma unroll
        for (int nt = 0; nt < 8; ++nt) {
            int cl = wn * 64 + nt * 8 + 2 * q;
            int r0 = m0 + wm * 64 + mt * 16 + g2;
            float bb0 = __ldg(b3 + n0 + cl);
            float bb1 = __ldg(b3 + n0 + cl + 1);
            float2 v0 = make_float2(acc[mt][nt][0] + bb0, acc[mt][nt][1] + bb1);
            float2 v1 = make_float2(acc[mt][nt][2] + bb0, acc[mt][nt][3] + bb1);
            *(float2*)(out + (size_t)r0 * D_OUT + n0 + cl)       = v0;
            *(float2*)(out + (size_t)(r0 + 8) * D_OUT + n0 + cl) = v1;
        }
    }
}

// ============================ host =========================================
extern "C" void kernel_launch(void* const* d_in, const int* in_sizes, int n_in,
                              void* d_out, int out_size) {
    (void)in_sizes; (void)n_in; (void)out_size;
    const float* x  = (const float*)d_in[0];
    const float* W1 = (const float*)d_in[1];
    const float* b1 = (const float*)d_in[2];
    const float* W2 = (const float*)d_in[3];
    const float* b2 = (const float*)d_in[4];
    const float* W3 = (const float*)d_in[5];
    const float* b3 = (const float*)d_in[6];
    float* out = (float*)d_out;

    void *pXh = nullptr, *pW1h = nullptr, *pW3h = nullptr, *px2h = nullptr;
    cudaGetSymbolAddress(&pXh,  g_Xh);
    cudaGetSymbolAddress(&pW1h, g_W1h);
    cudaGetSymbolAddress(&pW3h, g_W3h);
    cudaGetSymbolAddress(&px2h, g_x2h);

    const int smem1 = MB_OFF + 64;                    // 108608 B
    const int smem3 = MB3_OFF + 64;                   //  98368 B
    cudaFuncSetAttribute(fc1_kernel, cudaFuncAttributeMaxDynamicSharedMemorySize, smem1);
    cudaFuncSetAttribute(fc3_kernel, cudaFuncAttributeMaxDynamicSharedMemorySize, smem3);

    // single merged convert launch (X, W1, W3 -> fp16), 2 float4 per thread
    cvt_all_kernel<<<N4_ALL / CVT_BLK_F4, 256>>>(
        (const float4*)x, (const float4*)W1, (const float4*)W3,
        (uint2*)pXh, (uint2*)pW1h, (uint2*)pW3h);

    fc1_kernel<<<dim3(NH1 / BN, NROWS / BM), NTHR, smem1>>>(
        (const __half*)pXh, (const __half*)pW1h, b1, W2, b2, (__half*)px2h);
    fc3_kernel<<<dim3(D_OUT / BN, NROWS / BM), NTHR, smem3>>>(
        (const __half*)px2h, (const __half*)pW3h, b3, out);
}

// round 13
// speedup vs baseline: 1.0399x; 1.0013x over previous
#include <cuda_runtime.h>
#include <cuda_fp16.h>
#include <cstdint>
#include <cstddef>

// ============================ problem constants ============================
#define D_IN   1024
#define NH1    4096
#define NH2    512
#define D_OUT  256
#define NROWS  16384

// ============================ tiling =======================================
#define BM 128
#define BN 128
#define BK 64                        // fp16: row = 128B
#define NSTG 3
#define STAGE_B 32768                // (BM+BN)*BK*2 bytes
#define B_OFF   16384                // B tile offset within a stage
#define NTHR 128                     // 4 warps, warp tile 64x64
#define NC1  (D_IN / BK)             // 16 k-chunks (fc1)
#define NC3  (NH2 / BK)              // 8 k-chunks (fc3)
#define ES_OFF 98304                 // epilogue buffer (3 stages end)
#define MB_OFF 108544                // fc1 mbarriers: full[3] then empty[3]
#define MB3_OFF 98304                // fc3 mbarriers

// cvt segment sizes (in float4 units); all multiples of 1024
#define N4_X  (NROWS * D_IN / 4)     // 4194304
#define N4_W1 (NH1 * D_IN / 4)       // 1048576
#define N4_W3 (D_OUT * NH2 / 4)      // 32768
#define N4_ALL (N4_X + N4_W1 + N4_W3)
#define CVT_BLK_F4 1024              // float4 per block (256 thr x 4 -> MLP=4)

// ============================ scratch ======================================
__device__ __align__(1024) __half g_Xh [NROWS * D_IN];
__device__ __align__(1024) __half g_W1h[NH1 * D_IN];
__device__ __align__(1024) __half g_W3h[D_OUT * NH2];
__device__ __align__(1024) __half g_x2h[NROWS * NH2];

// ============================ device helpers ===============================
__device__ __forceinline__ uint32_t sm32(const void* p) {
    uint32_t a;
    asm("{ .reg .u64 t; cvta.to.shared.u64 t, %1; cvt.u32.u64 %0, t; }"
        : "=r"(a) : "l"(p));
    return a;
}
__device__ __forceinline__ void cpa16(uint32_t d, const void* s) {
    asm volatile("cp.async.cg.shared.global [%0], [%1], 16;" :: "r"(d), "l"(s));
}
__device__ __forceinline__ float4 ldcs4(const float4* p) {
    float4 v;
    asm volatile("ld.global.cs.v4.f32 {%0,%1,%2,%3}, [%4];"
        : "=f"(v.x), "=f"(v.y), "=f"(v.z), "=f"(v.w) : "l"(p));
    return v;
}

#define MBAR_INIT(addr, cnt) \
    asm volatile("mbarrier.init.shared.b64 [%0], %1;" :: "r"(addr), "r"(cnt) : "memory")
#define MBAR_ARRIVE(addr) \
    asm volatile("mbarrier.arrive.shared.b64 _, [%0];" :: "r"(addr) : "memory")
// .noinc is REQUIRED: the default form is self-balancing and never completes.
#define CP_MBAR_ARRIVE(addr) \
    asm volatile("cp.async.mbarrier.arrive.noinc.shared.b64 [%0];" :: "r"(addr) : "memory")

__device__ __forceinline__ void mbar_wait(uint32_t mbar, uint32_t parity) {
    asm volatile(
        "{\n\t.reg .pred P;\n\t"
        "LW_%=:\n\t"
        "mbarrier.try_wait.parity.acquire.cta.shared::cta.b64 P, [%0], %1, 0x989680;\n\t"
        "@P bra.uni LD_%=;\n\t"
        "bra.uni LW_%=;\n\t"
        "LD_%=:\n\t}"
        :: "r"(mbar), "r"(parity) : "memory");
}
// producer-side wait: post-wait writes are async-proxy (cp.async) only
__device__ __forceinline__ void mbar_wait_relaxed(uint32_t mbar, uint32_t parity) {
    asm volatile(
        "{\n\t.reg .pred P;\n\t"
        "LW_%=:\n\t"
        "mbarrier.try_wait.parity.relaxed.cta.shared::cta.b64 P, [%0], %1, 0x989680;\n\t"
        "@P bra.uni LD_%=;\n\t"
        "bra.uni LW_%=;\n\t"
        "LD_%=:\n\t}"
        :: "r"(mbar), "r"(parity) : "memory");
}

__device__ __forceinline__ void ldsm4(uint32_t* d, uint32_t a) {
    asm volatile("ldmatrix.sync.aligned.m8n8.x4.shared.b16 {%0,%1,%2,%3}, [%4];"
        : "=r"(d[0]), "=r"(d[1]), "=r"(d[2]), "=r"(d[3]) : "r"(a));
}
__device__ __forceinline__ void mma16(float* c, const uint32_t* a, const uint32_t* b) {
    asm volatile("mma.sync.aligned.m16n8k16.row.col.f32.f16.f16.f32 "
        "{%0,%1,%2,%3}, {%4,%5,%6,%7}, {%8,%9}, {%0,%1,%2,%3};"
        : "+f"(c[0]), "+f"(c[1]), "+f"(c[2]), "+f"(c[3])
        : "r"(a[0]), "r"(a[1]), "r"(a[2]), "r"(a[3]), "r"(b[0]), "r"(b[1]));
}
__device__ __forceinline__ float sigm(float x) {
    return __fdividef(1.f, 1.f + __expf(-x));
}

// ============================ merged fp32 -> fp16 convert ==================
// One launch; 1024 float4 per block (4 per thread, independent -> MLP=4).
// Segment sizes are multiples of 1024, so each block maps to exactly one
// segment (block-uniform branch). fp32 sources are read once: .cs eviction
// keeps L2 free for the fp16 outputs fc1 re-reads.
__global__ void __launch_bounds__(256) cvt_all_kernel(
    const float4* __restrict__ x,
    const float4* __restrict__ w1,
    const float4* __restrict__ w3,
    uint2* __restrict__ xh,
    uint2* __restrict__ w1h,
    uint2* __restrict__ w3h)
{
    const int base = blockIdx.x * CVT_BLK_F4;
    const float4* s;
    uint2* d;
    int off;
    if (base < N4_X)              { s = x;  d = xh;  off = base; }
    else if (base < N4_X + N4_W1) { s = w1; d = w1h; off = base - N4_X; }
    else                          { s = w3; d = w3h; off = base - N4_X - N4_W1; }

    const int i0 = off + threadIdx.x;
    float4 v0 = ldcs4(s + i0);             // four independent loads in flight
    float4 v1 = ldcs4(s + i0 + 256);
    float4 v2 = ldcs4(s + i0 + 512);
    float4 v3 = ldcs4(s + i0 + 768);

    #pragma unroll
    for (int t = 0; t < 4; ++t) {
        float4 v = (t == 0) ? v0 : (t == 1) ? v1 : (t == 2) ? v2 : v3;
        __half2 h0 = __floats2half2_rn(v.x, v.y);
        __half2 h1 = __floats2half2_rn(v.z, v.w);
        uint2 o;
        o.x = *(uint32_t*)&h0;
        o.y = *(uint32_t*)&h1;
        d[i0 + t * 256] = o;
    }
}

// ============================ stage load ===================================
// smem element (row r, k): byte = r*128 + (((k>>3) ^ (r&7))<<4) + (k&7)*2
template<int KDIM>
__device__ __forceinline__ void stage_load(
    const __half* __restrict__ A, const __half* __restrict__ B,
    int m0, int n0, int kc, int s, uint32_t sb, int tid)
{
    const uint32_t so = sb + (uint32_t)(s * STAGE_B);
    #pragma unroll
    for (int i = 0; i < 8; ++i) {                 // A: 128 rows x 8 x 16B
        int id = tid + i * NTHR;
        int r = id >> 3, u = id & 7;
        cpa16(so + r * 128 + ((u ^ (r & 7)) << 4),
              A + (size_t)(m0 + r) * KDIM + kc * BK + u * 8);
    }
    #pragma unroll
    for (int i = 0; i < 8; ++i) {                 // B: 128 rows x 8 x 16B
        int id = tid + i * NTHR;
        int r = id >> 3, u = id & 7;
        cpa16(so + B_OFF + r * 128 + ((u ^ (r & 7)) << 4),
              B + (size_t)(n0 + r) * KDIM + kc * BK + u * 8);
    }
}

// ============================ fc1: R9 mbarrier pipeline (best measured) ====
// full[s]: 128 .noinc cp-completion arrivals; empty[s]: 4 warp arrivals.
// Warps track private (stage, parity) cursors -> no CTA-wide rendezvous in
// the k-loop; skew is absorbed by the ring instead of serialized.
__global__ void __launch_bounds__(NTHR, 2) fc1_kernel(
    const __half* __restrict__ X,  const __half* __restrict__ W1,
    const float* __restrict__ b1,  const float* __restrict__ W2,
    const float* __restrict__ b2,  __half* __restrict__ x2)
{
    extern __shared__ float sm[];
    const uint32_t sb = sm32(sm);
    const int tid = threadIdx.x, lane = tid & 31, wid = tid >> 5;
    const int wm = wid >> 1, wn = wid & 1;
    const int m0 = blockIdx.y * BM, n0 = blockIdx.x * BN;
    const uint32_t mbf = sb + MB_OFF;              // full[3]
    const uint32_t mbe = sb + MB_OFF + 24;         // empty[3]

    if (tid == 0) {
        #pragma unroll
        for (int s = 0; s < NSTG; ++s) {
            MBAR_INIT(mbf + 8 * s, NTHR);          // 128 .noinc cp-arrives
            MBAR_INIT(mbe + 8 * s, 4);             // one arrive per warp
        }
    }
    __syncthreads();

    const int lr = lane & 7, j = lane >> 3;
    const int jlow = j & 1, jhi = j >> 1;
    uint32_t baseA[4], baseB[4];
    #pragma unroll
    for (int mt = 0; mt < 4; ++mt)
        baseA[mt] = (uint32_t)((wm * 64 + mt * 16 + (jlow << 3) + lr) * 128);
    #pragma unroll
    for (int p = 0; p < 4; ++p)
        baseB[p] = (uint32_t)(B_OFF + (wn * 64 + (2 * p + jhi) * 8 + lr) * 128);

    float acc[4][8][4];
    #pragma unroll
    for (int i = 0; i < 4; ++i)
        #pragma unroll
        for (int j2 = 0; j2 < 8; ++j2)
            #pragma unroll
            for (int k = 0; k < 4; ++k) acc[i][j2][k] = 0.f;

    // ---- prologue: fill stages 0,1 ----
    stage_load<D_IN>(X, W1, m0, n0, 0, 0, sb, tid);
    CP_MBAR_ARRIVE(mbf + 0);
    stage_load<D_IN>(X, W1, m0, n0, 1, 1, sb, tid);
    CP_MBAR_ARRIVE(mbf + 8);

    int lc = 2;                                    // next chunk to load
    #pragma unroll 1
    for (int c = 0; c < NC1; ++c) {
        // ---- load-ahead chunk lc ----
        if (lc < NC1) {
            const int lf = lc / NSTG;              // fill round
            const int lss = lc - lf * NSTG;        // its stage
            if (lc >= NSTG) mbar_wait(mbe + 8 * lss, (uint32_t)((lf - 1) & 1));
            stage_load<D_IN>(X, W1, m0, n0, lc, lss, sb, tid);
            CP_MBAR_ARRIVE(mbf + 8 * lss);
            ++lc;
        }

        // ---- consume chunk c ----
        const int cf = c / NSTG;
        const int cs = c - cf * NSTG;
        mbar_wait(mbf + 8 * cs, (uint32_t)(cf & 1));

        const uint32_t stg = sb + (uint32_t)cs * STAGE_B;
        #pragma unroll
        for (int ks = 0; ks < 4; ++ks) {
            const uint32_t swzA = (uint32_t)(((2 * ks + jhi) ^ lr) << 4);
            const uint32_t swzB = (uint32_t)(((2 * ks + jlow) ^ lr) << 4);
            uint32_t a[4][4], b[4][4];
            #pragma unroll
            for (int mt = 0; mt < 4; ++mt) ldsm4(a[mt], stg + baseA[mt] + swzA);
            #pragma unroll
            for (int p = 0; p < 4; ++p)    ldsm4(b[p],  stg + baseB[p] + swzB);
            #pragma unroll
            for (int mt = 0; mt < 4; ++mt) {
                #pragma unroll
                for (int p = 0; p < 4; ++p) {
                    mma16(acc[mt][2 * p],     a[mt], &b[p][0]);
                    mma16(acc[mt][2 * p + 1], a[mt], &b[p][2]);
                }
            }
        }
        __syncwarp();
        if (lane == 0) MBAR_ARRIVE(mbe + 8 * cs);  // warp done with stage cs
    }

    // -------- fused epilogue: bias+sigmoid -> grouped dot (quad shfl) ------
    const int q = lane & 3, g2 = lane >> 2;
    const int ntile = blockIdx.x;
    float* es = sm + ES_OFF / 4;                   // dedicated buffer

    float b1v[16], w2v[16];
    #pragma unroll
    for (int nt = 0; nt < 8; ++nt) {
        int cidx = n0 + wn * 64 + nt * 8 + 2 * q;
        b1v[2 * nt]     = __ldg(b1 + cidx);
        b1v[2 * nt + 1] = __ldg(b1 + cidx + 1);
        w2v[2 * nt]     = __ldg(W2 + cidx);
        w2v[2 * nt + 1] = __ldg(W2 + cidx + 1);
    }
    const float b2v0 = __ldg(b2 + ntile * 16 + wn * 8 + q);
    const float b2v1 = __ldg(b2 + ntile * 16 + wn * 8 + q + 4);

    #pragma unroll
    for (int mt = 0; mt < 4; ++mt) {
        #pragma unroll
        for (int nt = 0; nt < 8; ++nt) {
            float h00 = sigm(acc[mt][nt][0] + b1v[2 * nt]);
            float h01 = sigm(acc[mt][nt][1] + b1v[2 * nt + 1]);
            float h10 = sigm(acc[mt][nt][2] + b1v[2 * nt]);
            float h11 = sigm(acc[mt][nt][3] + b1v[2 * nt + 1]);
            float p0 = h00 * w2v[2 * nt] + h01 * w2v[2 * nt + 1];
            float p1 = h10 * w2v[2 * nt] + h11 * w2v[2 * nt + 1];
            p0 += __shfl_xor_sync(0xffffffffu, p0, 1);
            p0 += __shfl_xor_sync(0xffffffffu, p0, 2);
            p1 += __shfl_xor_sync(0xffffffffu, p1, 1);
            p1 += __shfl_xor_sync(0xffffffffu, p1, 2);
            if (q == (nt & 3)) {
                int g  = wn * 8 + nt;              // 16 groups per CTA
                int r0 = wm * 64 + mt * 16 + g2;
                float bv = (nt < 4) ? b2v0 : b2v1;
                es[r0 * 20 + g]       = sigm(p0 + bv);
                es[(r0 + 8) * 20 + g] = sigm(p1 + bv);
            }
        }
    }
    __syncthreads();

    // coalesced fp16 store: 128 rows x 16 groups; 1 thread per row
    {
        const float* e = es + tid * 20;
        __half2 h0 = __floats2half2_rn(e[0],  e[1]);
        __half2 h1 = __floats2half2_rn(e[2],  e[3]);
        __half2 h2 = __floats2half2_rn(e[4],  e[5]);
        __half2 h3 = __floats2half2_rn(e[6],  e[7]);
        __half2 h4 = __floats2half2_rn(e[8],  e[9]);
        __half2 h5 = __floats2half2_rn(e[10], e[11]);
        __half2 h6 = __floats2half2_rn(e[12], e[13]);
        __half2 h7 = __floats2half2_rn(e[14], e[15]);
        uint4 o0, o1;
        o0.x = *(uint32_t*)&h0; o0.y = *(uint32_t*)&h1;
        o0.z = *(uint32_t*)&h2; o0.w = *(uint32_t*)&h3;
        o1.x = *(uint32_t*)&h4; o1.y = *(uint32_t*)&h5;
        o1.z = *(uint32_t*)&h6; o1.w = *(uint32_t*)&h7;
        __half* dst = x2 + (size_t)(m0 + tid) * NH2 + ntile * 16;
        *(uint4*)dst       = o0;
        *(uint4*)(dst + 8) = o1;
    }
}

// ============================ fc3: mbar pipeline (R10, measured better) ====
__global__ void __launch_bounds__(NTHR, 2) fc3_kernel(
    const __half* __restrict__ A,  const __half* __restrict__ W3,
    const float* __restrict__ b3,  float* __restrict__ out)
{
    extern __shared__ float sm[];
    const uint32_t sb = sm32(sm);
    const int tid = threadIdx.x, lane = tid & 31, wid = tid >> 5;
    const int wm = wid >> 1, wn = wid & 1;
    const int m0 = blockIdx.y * BM, n0 = blockIdx.x * BN;
    const uint32_t mbf = sb + MB3_OFF;
    const uint32_t mbe = sb + MB3_OFF + 24;

    if (tid == 0) {
        #pragma unroll
        for (int s = 0; s < NSTG; ++s) {
            MBAR_INIT(mbf + 8 * s, NTHR);
            MBAR_INIT(mbe + 8 * s, 4);
        }
    }
    __syncthreads();

    const int lr = lane & 7, j = lane >> 3;
    const int jlow = j & 1, jhi = j >> 1;
    uint32_t baseA[4], baseB[4];
    #pragma unroll
    for (int mt = 0; mt < 4; ++mt)
        baseA[mt] = (uint32_t)((wm * 64 + mt * 16 + (jlow << 3) + lr) * 128);
    #pragma unroll
    for (int p = 0; p < 4; ++p)
        baseB[p] = (uint32_t)(B_OFF + (wn * 64 + (2 * p + jhi) * 8 + lr) * 128);

    float acc[4][8][4];
    #pragma unroll
    for (int i = 0; i < 4; ++i)
        #pragma unroll
        for (int j2 = 0; j2 < 8; ++j2)
            #pragma unroll
            for (int k = 0; k < 4; ++k) acc[i][j2][k] = 0.f;

    auto do_ks = [&](uint32_t stg, int kse) {
        const uint32_t swzA = (uint32_t)(((2 * kse + jhi) ^ lr) << 4);
        const uint32_t swzB = (uint32_t)(((2 * kse + jlow) ^ lr) << 4);
        uint32_t a[4][4], b[4][4];
        #pragma unroll
        for (int mt = 0; mt < 4; ++mt) ldsm4(a[mt], stg + baseA[mt] + swzA);
        #pragma unroll
        for (int p = 0; p < 4; ++p)    ldsm4(b[p],  stg + baseB[p] + swzB);
        #pragma unroll
        for (int mt = 0; mt < 4; ++mt) {
            #pragma unroll
            for (int p = 0; p < 4; ++p) {
                mma16(acc[mt][2 * p],     a[mt], &b[p][0]);
                mma16(acc[mt][2 * p + 1], a[mt], &b[p][2]);
            }
        }
    };

    stage_load<NH2>(A, W3, m0, n0, 0, 0, sb, tid);
    CP_MBAR_ARRIVE(mbf + 0);
    stage_load<NH2>(A, W3, m0, n0, 1, 1, sb, tid);
    CP_MBAR_ARRIVE(mbf + 8);

    int lc = 2;
    #pragma unroll 1
    for (int c = 0; c < NC3; ++c) {
        const int cf = c / NSTG;
        const int cs = c - cf * NSTG;
        mbar_wait(mbf + 8 * cs, (uint32_t)(cf & 1));
        const uint32_t stg = sb + (uint32_t)cs * STAGE_B;

        do_ks(stg, wid & 3);
        if (lc < NC3) {
            const int lf = lc / NSTG;
            const int lss = lc - lf * NSTG;
            if (lc >= NSTG) mbar_wait_relaxed(mbe + 8 * lss, (uint32_t)((lf - 1) & 1));
            stage_load<NH2>(A, W3, m0, n0, lc, lss, sb, tid);
            CP_MBAR_ARRIVE(mbf + 8 * lss);
            ++lc;
        }
        do_ks(stg, (wid + 1) & 3);
        do_ks(stg, (wid + 2) & 3);
        do_ks(stg, (wid + 3) & 3);

        __syncwarp();
        if (lane == 0) MBAR_ARRIVE(mbe + 8 * cs);
    }

    const int q = lane & 3, g2 = lane >> 2;
    #pragma unroll
    for (int mt = 0; mt < 4; ++mt) {
        #pragma unroll
        for (int nt = 0; nt < 8; ++nt) {
            int cl = wn * 64 + nt * 8 + 2 * q;
            int r0 = m0 + wm * 64 + mt * 16 + g2;
            float bb0 = __ldg(b3 + n0 + cl);
            float bb1 = __ldg(b3 + n0 + cl + 1);
            float2 v0 = make_float2(acc[mt][nt][0] + bb0, acc[mt][nt][1] + bb1);
            float2 v1 = make_float2(acc[mt][nt][2] + bb0, acc[mt][nt][3] + bb1);
            *(float2*)(out + (size_t)r0 * D_OUT + n0 + cl)       = v0;
            *(float2*)(out + (size_t)(r0 + 8) * D_OUT + n0 + cl) = v1;
        }
    }
}

// ============================ host =========================================
extern "C" void kernel_launch(void* const* d_in, const int* in_sizes, int n_in,
                              void* d_out, int out_size) {
    (void)in_sizes; (void)n_in; (void)out_size;
    const float* x  = (const float*)d_in[0];
    const float* W1 = (const float*)d_in[1];
    const float* b1 = (const float*)d_in[2];
    const float* W2 = (const float*)d_in[3];
    const float* b2 = (const float*)d_in[4];
    const float* W3 = (const float*)d_in[5];
    const float* b3 = (const float*)d_in[6];
    float* out = (float*)d_out;

    void *pXh = nullptr, *pW1h = nullptr, *pW3h = nullptr, *px2h = nullptr;
    cudaGetSymbolAddress(&pXh,  g_Xh);
    cudaGetSymbolAddress(&pW1h, g_W1h);
    cudaGetSymbolAddress(&pW3h, g_W3h);
    cudaGetSymbolAddress(&px2h, g_x2h);

    const int smem1 = MB_OFF + 64;                    // 108608 B
    const int smem3 = MB3_OFF + 64;                   //  98368 B
    cudaFuncSetAttribute(fc1_kernel, cudaFuncAttributeMaxDynamicSharedMemorySize, smem1);
    cudaFuncSetAttribute(fc3_kernel, cudaFuncAttributeMaxDynamicSharedMemorySize, smem3);

    // single merged convert launch (X, W1, W3 -> fp16), 4 float4 per thread
    cvt_all_kernel<<<N4_ALL / CVT_BLK_F4, 256>>>(
        (const float4*)x, (const float4*)W1, (const float4*)W3,
        (uint2*)pXh, (uint2*)pW1h, (uint2*)pW3h);

    fc1_kernel<<<dim3(NH1 / BN, NROWS / BM), NTHR, smem1>>>(
        (const __half*)pXh, (const __half*)pW1h, b1, W2, b2, (__half*)px2h);
    fc3_kernel<<<dim3(D_OUT / BN, NROWS / BM), NTHR, smem3>>>(
        (const __half*)px2h, (const __half*)pW3h, b3, out);
}

// round 14
// speedup vs baseline: 1.0405x; 1.0006x over previous
#include <cuda_runtime.h>
#include <cuda_fp16.h>
#include <cstdint>
#include <cstddef>

// ============================ problem constants ============================
#define D_IN   1024
#define NH1    4096
#define NH2    512
#define D_OUT  256
#define NROWS  16384

// ============================ tiling =======================================
#define BM 128
#define BN 128
#define BK 64                        // fp16: row = 128B
#define NSTG 3
#define STAGE_B 32768                // (BM+BN)*BK*2 bytes
#define B_OFF   16384                // B tile offset within a stage
#define NTHR 128                     // 4 warps, warp tile 64x64
#define NC1  (D_IN / BK)             // 16 k-chunks (fc1)
#define NC3  (NH2 / BK)              // 8 k-chunks (fc3)
#define ES_OFF 98304                 // epilogue buffer (3 stages end)
#define MB_OFF 108544                // fc1 mbarriers: full[3] then empty[3]
#define MB3_OFF 98304                // fc3 mbarriers

// cvt segment sizes (in float4 units); all multiples of 1024
#define N4_X  (NROWS * D_IN / 4)     // 4194304
#define N4_W1 (NH1 * D_IN / 4)       // 1048576
#define N4_W3 (D_OUT * NH2 / 4)      // 32768
#define N4_ALL (N4_X + N4_W1 + N4_W3)
#define CVT_BLK_F4 1024              // float4 per block (256 thr x 4 -> MLP=4)

// ============================ scratch ======================================
__device__ __align__(1024) __half g_Xh [NROWS * D_IN];
__device__ __align__(1024) __half g_W1h[NH1 * D_IN];
__device__ __align__(1024) __half g_W3h[D_OUT * NH2];
__device__ __align__(1024) __half g_x2h[NROWS * NH2];

// ============================ device helpers ===============================
__device__ __forceinline__ uint32_t sm32(const void* p) {
    uint32_t a;
    asm("{ .reg .u64 t; cvta.to.shared.u64 t, %1; cvt.u32.u64 %0, t; }"
        : "=r"(a) : "l"(p));
    return a;
}
__device__ __forceinline__ void cpa16(uint32_t d, const void* s) {
    asm volatile("cp.async.cg.shared.global [%0], [%1], 16;" :: "r"(d), "l"(s));
}
__device__ __forceinline__ float4 ldcs4(const float4* p) {
    float4 v;
    asm volatile("ld.global.cs.v4.f32 {%0,%1,%2,%3}, [%4];"
        : "=f"(v.x), "=f"(v.y), "=f"(v.z), "=f"(v.w) : "l"(p));
    return v;
}

#define MBAR_INIT(addr, cnt) \
    asm volatile("mbarrier.init.shared.b64 [%0], %1;" :: "r"(addr), "r"(cnt) : "memory")
#define MBAR_ARRIVE(addr) \
    asm volatile("mbarrier.arrive.shared.b64 _, [%0];" :: "r"(addr) : "memory")
// .noinc is REQUIRED: the default form is self-balancing and never completes.
#define CP_MBAR_ARRIVE(addr) \
    asm volatile("cp.async.mbarrier.arrive.noinc.shared.b64 [%0];" :: "r"(addr) : "memory")

__device__ __forceinline__ void mbar_wait(uint32_t mbar, uint32_t parity) {
    asm volatile(
        "{\n\t.reg .pred P;\n\t"
        "LW_%=:\n\t"
        "mbarrier.try_wait.parity.acquire.cta.shared::cta.b64 P, [%0], %1, 0x989680;\n\t"
        "@P bra.uni LD_%=;\n\t"
        "bra.uni LW_%=;\n\t"
        "LD_%=:\n\t}"
        :: "r"(mbar), "r"(parity) : "memory");
}
// producer-side wait: post-wait writes are async-proxy (cp.async) only
__device__ __forceinline__ void mbar_wait_relaxed(uint32_t mbar, uint32_t parity) {
    asm volatile(
        "{\n\t.reg .pred P;\n\t"
        "LW_%=:\n\t"
        "mbarrier.try_wait.parity.relaxed.cta.shared::cta.b64 P, [%0], %1, 0x989680;\n\t"
        "@P bra.uni LD_%=;\n\t"
        "bra.uni LW_%=;\n\t"
        "LD_%=:\n\t}"
        :: "r"(mbar), "r"(parity) : "memory");
}

__device__ __forceinline__ void ldsm4(uint32_t* d, uint32_t a) {
    asm volatile("ldmatrix.sync.aligned.m8n8.x4.shared.b16 {%0,%1,%2,%3}, [%4];"
        : "=r"(d[0]), "=r"(d[1]), "=r"(d[2]), "=r"(d[3]) : "r"(a));
}
__device__ __forceinline__ void mma16(float* c, const uint32_t* a, const uint32_t* b) {
    asm volatile("mma.sync.aligned.m16n8k16.row.col.f32.f16.f16.f32 "
        "{%0,%1,%2,%3}, {%4,%5,%6,%7}, {%8,%9}, {%0,%1,%2,%3};"
        : "+f"(c[0]), "+f"(c[1]), "+f"(c[2]), "+f"(c[3])
        : "r"(a[0]), "r"(a[1]), "r"(a[2]), "r"(a[3]), "r"(b[0]), "r"(b[1]));
}
__device__ __forceinline__ float sigm(float x) {
    return __fdividef(1.f, 1.f + __expf(-x));
}

// ============================ merged fp32 -> fp16 convert ==================
// One launch; 1024 float4 per block (4 per thread, independent -> MLP=4).
// Segment sizes are multiples of 1024 -> block-uniform branch. .cs reads:
// sources are read once; keep L2 for the fp16 outputs fc1 re-reads.
__global__ void __launch_bounds__(256) cvt_all_kernel(
    const float4* __restrict__ x,
    const float4* __restrict__ w1,
    const float4* __restrict__ w3,
    uint2* __restrict__ xh,
    uint2* __restrict__ w1h,
    uint2* __restrict__ w3h)
{
    const int base = blockIdx.x * CVT_BLK_F4;
    const float4* s;
    uint2* d;
    int off;
    if (base < N4_X)              { s = x;  d = xh;  off = base; }
    else if (base < N4_X + N4_W1) { s = w1; d = w1h; off = base - N4_X; }
    else                          { s = w3; d = w3h; off = base - N4_X - N4_W1; }

    const int i0 = off + threadIdx.x;
    float4 v0 = ldcs4(s + i0);             // four independent loads in flight
    float4 v1 = ldcs4(s + i0 + 256);
    float4 v2 = ldcs4(s + i0 + 512);
    float4 v3 = ldcs4(s + i0 + 768);

    #pragma unroll
    for (int t = 0; t < 4; ++t) {
        float4 v = (t == 0) ? v0 : (t == 1) ? v1 : (t == 2) ? v2 : v3;
        __half2 h0 = __floats2half2_rn(v.x, v.y);
        __half2 h1 = __floats2half2_rn(v.z, v.w);
        uint2 o;
        o.x = *(uint32_t*)&h0;
        o.y = *(uint32_t*)&h1;
        d[i0 + t * 256] = o;
    }
}

// ============================ stage load ===================================
// smem element (row r, k): byte = r*128 + (((k>>3) ^ (r&7))<<4) + (k&7)*2
template<int KDIM>
__device__ __forceinline__ void stage_load(
    const __half* __restrict__ A, const __half* __restrict__ B,
    int m0, int n0, int kc, int s, uint32_t sb, int tid)
{
    const uint32_t so = sb + (uint32_t)(s * STAGE_B);
    #pragma unroll
    for (int i = 0; i < 8; ++i) {                 // A: 128 rows x 8 x 16B
        int id = tid + i * NTHR;
        int r = id >> 3, u = id & 7;
        cpa16(so + r * 128 + ((u ^ (r & 7)) << 4),
              A + (size_t)(m0 + r) * KDIM + kc * BK + u * 8);
    }
    #pragma unroll
    for (int i = 0; i < 8; ++i) {                 // B: 128 rows x 8 x 16B
        int id = tid + i * NTHR;
        int r = id >> 3, u = id & 7;
        cpa16(so + B_OFF + r * 128 + ((u ^ (r & 7)) << 4),
              B + (size_t)(n0 + r) * KDIM + kc * BK + u * 8);
    }
}

// ============================ fc1: R9 mbarrier pipeline + relaxed producer =
// full[s]: 128 .noinc cp-completion arrivals; empty[s]: 4 warp arrivals.
// Warps track private (stage, parity) cursors -> no CTA-wide rendezvous in
// the k-loop. Producer empty-wait is RELAXED (post-wait writes are cp.async).
__global__ void __launch_bounds__(NTHR, 2) fc1_kernel(
    const __half* __restrict__ X,  const __half* __restrict__ W1,
    const float* __restrict__ b1,  const float* __restrict__ W2,
    const float* __restrict__ b2,  __half* __restrict__ x2)
{
    extern __shared__ float sm[];
    const uint32_t sb = sm32(sm);
    const int tid = threadIdx.x, lane = tid & 31, wid = tid >> 5;
    const int wm = wid >> 1, wn = wid & 1;
    const int m0 = blockIdx.y * BM, n0 = blockIdx.x * BN;
    const uint32_t mbf = sb + MB_OFF;              // full[3]
    const uint32_t mbe = sb + MB_OFF + 24;         // empty[3]

    if (tid == 0) {
        #pragma unroll
        for (int s = 0; s < NSTG; ++s) {
            MBAR_INIT(mbf + 8 * s, NTHR);          // 128 .noinc cp-arrives
            MBAR_INIT(mbe + 8 * s, 4);             // one arrive per warp
        }
    }
    __syncthreads();

    const int lr = lane & 7, j = lane >> 3;
    const int jlow = j & 1, jhi = j >> 1;
    uint32_t baseA[4], baseB[4];
    #pragma unroll
    for (int mt = 0; mt < 4; ++mt)
        baseA[mt] = (uint32_t)((wm * 64 + mt * 16 + (jlow << 3) + lr) * 128);
    #pragma unroll
    for (int p = 0; p < 4; ++p)
        baseB[p] = (uint32_t)(B_OFF + (wn * 64 + (2 * p + jhi) * 8 + lr) * 128);

    float acc[4][8][4];
    #pragma unroll
    for (int i = 0; i < 4; ++i)
        #pragma unroll
        for (int j2 = 0; j2 < 8; ++j2)
            #pragma unroll
            for (int k = 0; k < 4; ++k) acc[i][j2][k] = 0.f;

    // ---- prologue: fill stages 0,1 ----
    stage_load<D_IN>(X, W1, m0, n0, 0, 0, sb, tid);
    CP_MBAR_ARRIVE(mbf + 0);
    stage_load<D_IN>(X, W1, m0, n0, 1, 1, sb, tid);
    CP_MBAR_ARRIVE(mbf + 8);

    int lc = 2;                                    // next chunk to load
    #pragma unroll 1
    for (int c = 0; c < NC1; ++c) {
        // ---- load-ahead chunk lc ----
        if (lc < NC1) {
            const int lf = lc / NSTG;              // fill round
            const int lss = lc - lf * NSTG;        // its stage
            if (lc >= NSTG) mbar_wait_relaxed(mbe + 8 * lss, (uint32_t)((lf - 1) & 1));
            stage_load<D_IN>(X, W1, m0, n0, lc, lss, sb, tid);
            CP_MBAR_ARRIVE(mbf + 8 * lss);
            ++lc;
        }

        // ---- consume chunk c ----
        const int cf = c / NSTG;
        const int cs = c - cf * NSTG;
        mbar_wait(mbf + 8 * cs, (uint32_t)(cf & 1));

        const uint32_t stg = sb + (uint32_t)cs * STAGE_B;
        #pragma unroll
        for (int ks = 0; ks < 4; ++ks) {
            const uint32_t swzA = (uint32_t)(((2 * ks + jhi) ^ lr) << 4);
            const uint32_t swzB = (uint32_t)(((2 * ks + jlow) ^ lr) << 4);
            uint32_t a[4][4], b[4][4];
            #pragma unroll
            for (int mt = 0; mt < 4; ++mt) ldsm4(a[mt], stg + baseA[mt] + swzA);
            #pragma unroll
            for (int p = 0; p < 4; ++p)    ldsm4(b[p],  stg + baseB[p] + swzB);
            #pragma unroll
            for (int mt = 0; mt < 4; ++mt) {
                #pragma unroll
                for (int p = 0; p < 4; ++p) {
                    mma16(acc[mt][2 * p],     a[mt], &b[p][0]);
                    mma16(acc[mt][2 * p + 1], a[mt], &b[p][2]);
                }
            }
        }
        __syncwarp();
        if (lane == 0) MBAR_ARRIVE(mbe + 8 * cs);  // warp done with stage cs
    }

    // -------- fused epilogue: bias+sigmoid -> grouped dot (quad shfl) ------
    const int q = lane & 3, g2 = lane >> 2;
    const int ntile = blockIdx.x;
    float* es = sm + ES_OFF / 4;                   // dedicated buffer

    // batch all epilogue constants ahead of the acc-dependent math
    float b1v[16], w2v[16];
    #pragma unroll
    for (int nt = 0; nt < 8; ++nt) {
        int cidx = n0 + wn * 64 + nt * 8 + 2 * q;
        b1v[2 * nt]     = __ldg(b1 + cidx);
        b1v[2 * nt + 1] = __ldg(b1 + cidx + 1);
    }
    #pragma unroll
    for (int nt = 0; nt < 8; ++nt) {
        int cidx = n0 + wn * 64 + nt * 8 + 2 * q;
        w2v[2 * nt]     = __ldg(W2 + cidx);
        w2v[2 * nt + 1] = __ldg(W2 + cidx + 1);
    }
    const float b2v0 = __ldg(b2 + ntile * 16 + wn * 8 + q);
    const float b2v1 = __ldg(b2 + ntile * 16 + wn * 8 + q + 4);

    #pragma unroll
    for (int mt = 0; mt < 4; ++mt) {
        #pragma unroll
        for (int nt = 0; nt < 8; ++nt) {
            float h00 = sigm(acc[mt][nt][0] + b1v[2 * nt]);
            float h01 = sigm(acc[mt][nt][1] + b1v[2 * nt + 1]);
            float h10 = sigm(acc[mt][nt][2] + b1v[2 * nt]);
            float h11 = sigm(acc[mt][nt][3] + b1v[2 * nt + 1]);
            float p0 = h00 * w2v[2 * nt] + h01 * w2v[2 * nt + 1];
            float p1 = h10 * w2v[2 * nt] + h11 * w2v[2 * nt + 1];
            p0 += __shfl_xor_sync(0xffffffffu, p0, 1);
            p0 += __shfl_xor_sync(0xffffffffu, p0, 2);
            p1 += __shfl_xor_sync(0xffffffffu, p1, 1);
            p1 += __shfl_xor_sync(0xffffffffu, p1, 2);
            if (q == (nt & 3)) {
                int g  = wn * 8 + nt;              // 16 groups per CTA
                int r0 = wm * 64 + mt * 16 + g2;
                float bv = (nt < 4) ? b2v0 : b2v1;
                es[r0 * 20 + g]       = sigm(p0 + bv);
                es[(r0 + 8) * 20 + g] = sigm(p1 + bv);
            }
        }
    }
    __syncthreads();

    // coalesced fp16 store: 128 rows x 16 groups; 1 thread per row
    {
        const float* e = es + tid * 20;
        __half2 h0 = __floats2half2_rn(e[0],  e[1]);
        __half2 h1 = __floats2half2_rn(e[2],  e[3]);
        __half2 h2 = __floats2half2_rn(e[4],  e[5]);
        __half2 h3 = __floats2half2_rn(e[6],  e[7]);
        __half2 h4 = __floats2half2_rn(e[8],  e[9]);
        __half2 h5 = __floats2half2_rn(e[10], e[11]);
        __half2 h6 = __floats2half2_rn(e[12], e[13]);
        __half2 h7 = __floats2half2_rn(e[14], e[15]);
        uint4 o0, o1;
        o0.x = *(uint32_t*)&h0; o0.y = *(uint32_t*)&h1;
        o0.z = *(uint32_t*)&h2; o0.w = *(uint32_t*)&h3;
        o1.x = *(uint32_t*)&h4; o1.y = *(uint32_t*)&h5;
        o1.z = *(uint32_t*)&h6; o1.w = *(uint32_t*)&h7;
        __half* dst = x2 + (size_t)(m0 + tid) * NH2 + ntile * 16;
        *(uint4*)dst       = o0;
        *(uint4*)(dst + 8) = o1;
    }
}

// ============================ fc3: mbar pipeline (R10, measured better) ====
__global__ void __launch_bounds__(NTHR, 2) fc3_kernel(
    const __half* __restrict__ A,  const __half* __restrict__ W3,
    const float* __restrict__ b3,  float* __restrict__ out)
{
    extern __shared__ float sm[];
    const uint32_t sb = sm32(sm);
    const int tid = threadIdx.x, lane = tid & 31, wid = tid >> 5;
    const int wm = wid >> 1, wn = wid & 1;
    const int m0 = blockIdx.y * BM, n0 = blockIdx.x * BN;
    const uint32_t mbf = sb + MB3_OFF;
    const uint32_t mbe = sb + MB3_OFF + 24;

    if (tid == 0) {
        #pragma unroll
        for (int s = 0; s < NSTG; ++s) {
            MBAR_INIT(mbf + 8 * s, NTHR);
            MBAR_INIT(mbe + 8 * s, 4);
        }
    }
    __syncthreads();

    const int lr = lane & 7, j = lane >> 3;
    const int jlow = j & 1, jhi = j >> 1;
    uint32_t baseA[4], baseB[4];
    #pragma unroll
    for (int mt = 0; mt < 4; ++mt)
        baseA[mt] = (uint32_t)((wm * 64 + mt * 16 + (jlow << 3) + lr) * 128);
    #pragma unroll
    for (int p = 0; p < 4; ++p)
        baseB[p] = (uint32_t)(B_OFF + (wn * 64 + (2 * p + jhi) * 8 + lr) * 128);

    float acc[4][8][4];
    #pragma unroll
    for (int i = 0; i < 4; ++i)
        #pragma unroll
        for (int j2 = 0; j2 < 8; ++j2)
            #pragma unroll
            for (int k = 0; k < 4; ++k) acc[i][j2][k] = 0.f;

    auto do_ks = [&](uint32_t stg, int kse) {
        const uint32_t swzA = (uint32_t)(((2 * kse + jhi) ^ lr) << 4);
        const uint32_t swzB = (uint32_t)(((2 * kse + jlow) ^ lr) << 4);
        uint32_t a[4][4], b[4][4];
        #pragma unroll
        for (int mt = 0; mt < 4; ++mt) ldsm4(a[mt], stg + baseA[mt] + swzA);
        #pragma unroll
        for (int p = 0; p < 4; ++p)    ldsm4(b[p],  stg + baseB[p] + swzB);
        #pragma unroll
        for (int mt = 0; mt < 4; ++mt) {
            #pragma unroll
            for (int p = 0; p < 4; ++p) {
                mma16(acc[mt][2 * p],     a[mt], &b[p][0]);
                mma16(acc[mt][2 * p + 1], a[mt], &b[p][2]);
            }
        }
    };

    stage_load<NH2>(A, W3, m0, n0, 0, 0, sb, tid);
    CP_MBAR_ARRIVE(mbf + 0);
    stage_load<NH2>(A, W3, m0, n0, 1, 1, sb, tid);
    CP_MBAR_ARRIVE(mbf + 8);

    int lc = 2;
    #pragma unroll 1
    for (int c = 0; c < NC3; ++c) {
        const int cf = c / NSTG;
        const int cs = c - cf * NSTG;
        mbar_wait(mbf + 8 * cs, (uint32_t)(cf & 1));
        const uint32_t stg = sb + (uint32_t)cs * STAGE_B;

        do_ks(stg, wid & 3);
        if (lc < NC3) {
            const int lf = lc / NSTG;
            const int lss = lc - lf * NSTG;
            if (lc >= NSTG) mbar_wait_relaxed(mbe + 8 * lss, (uint32_t)((lf - 1) & 1));
            stage_load<NH2>(A, W3, m0, n0, lc, lss, sb, tid);
            CP_MBAR_ARRIVE(mbf + 8 * lss);
            ++lc;
        }
        do_ks(stg, (wid + 1) & 3);
        do_ks(stg, (wid + 2) & 3);
        do_ks(stg, (wid + 3) & 3);

        __syncwarp();
        if (lane == 0) MBAR_ARRIVE(mbe + 8 * cs);
    }

    const int q = lane & 3, g2 = lane >> 2;
    #pragma unroll
    for (int mt = 0; mt < 4; ++mt) {
        #pragma unroll
        for (int nt = 0; nt < 8; ++nt) {
            int cl = wn * 64 + nt * 8 + 2 * q;
            int r0 = m0 + wm * 64 + mt * 16 + g2;
            float bb0 = __ldg(b3 + n0 + cl);
            float bb1 = __ldg(b3 + n0 + cl + 1);
            float2 v0 = make_float2(acc[mt][nt][0] + bb0, acc[mt][nt][1] + bb1);
            float2 v1 = make_float2(acc[mt][nt][2] + bb0, acc[mt][nt][3] + bb1);
            *(float2*)(out + (size_t)r0 * D_OUT + n0 + cl)       = v0;
            *(float2*)(out + (size_t)(r0 + 8) * D_OUT + n0 + cl) = v1;
        }
    }
}

// ============================ host =========================================
extern "C" void kernel_launch(void* const* d_in, const int* in_sizes, int n_in,
                              void* d_out, int out_size) {
    (void)in_sizes; (void)n_in; (void)out_size;
    const float* x  = (const float*)d_in[0];
    const float* W1 = (const float*)d_in[1];
    const float* b1 = (const float*)d_in[2];
    const float* W2 = (const float*)d_in[3];
    const float* b2 = (const float*)d_in[4];
    const float* W3 = (const float*)d_in[5];
    const float* b3 = (const float*)d_in[6];
    float* out = (float*)d_out;

    void *pXh = nullptr, *pW1h = nullptr, *pW3h = nullptr, *px2h = nullptr;
    cudaGetSymbolAddress(&pXh,  g_Xh);
    cudaGetSymbolAddress(&pW1h, g_W1h);
    cudaGetSymbolAddress(&pW3h, g_W3h);
    cudaGetSymbolAddress(&px2h, g_x2h);

    const int smem1 = MB_OFF + 64;                    // 108608 B
    const int smem3 = MB3_OFF + 64;                   //  98368 B
    cudaFuncSetAttribute(fc1_kernel, cudaFuncAttributeMaxDynamicSharedMemorySize, smem1);
    cudaFuncSetAttribute(fc3_kernel, cudaFuncAttributeMaxDynamicSharedMemorySize, smem3);

    // single merged convert launch (X, W1, W3 -> fp16), 4 float4 per thread
    cvt_all_kernel<<<N4_ALL / CVT_BLK_F4, 256>>>(
        (const float4*)x, (const float4*)W1, (const float4*)W3,
        (uint2*)pXh, (uint2*)pW1h, (uint2*)pW3h);

    fc1_kernel<<<dim3(NH1 / BN, NROWS / BM), NTHR, smem1>>>(
        (const __half*)pXh, (const __half*)pW1h, b1, W2, b2, (__half*)px2h);
    fc3_kernel<<<dim3(D_OUT / BN, NROWS / BM), NTHR, smem3>>>(
        (const __half*)px2h, (const __half*)pW3h, b3, out);
}